// round 13
// baseline (speedup 1.0000x reference)
#include <cuda_runtime.h>
#include <cuda_fp16.h>
#include <math.h>
#include <stdint.h>

#define BSZ   2
#define SEQ   2048
#define DM    1024
#define NH    16
#define DK    64
#define RELN  (2*SEQ-1)   // 4095
#define MROWS (BSZ*SEQ)   // 4096
#define WSCALE 32.0f
#define INVWS  0.03125f

// ---------------- scratch (device globals; device-code access only) --------
__device__ float g_bias[NH*RELN];            // [h][rel + S-1]

__device__ uint32_t g_qhi_w[BSZ*NH*SEQ*(DK/2)];   // Q packed fp16 hi words
__device__ uint32_t g_qlo_w[BSZ*NH*SEQ*(DK/2)];
__device__ uint32_t g_khi_w[BSZ*NH*SEQ*(DK/2)];   // K packed words
__device__ uint32_t g_klo_w[BSZ*NH*SEQ*(DK/2)];
__device__ uint32_t g_vthi[BSZ*NH*DK*(SEQ/2)];    // V^T words [bh][d][u]
__device__ uint32_t g_vtlo[BSZ*NH*DK*(SEQ/2)];

__device__ __half g_xhi[MROWS*DM];   // activations hi/lo (fp16)
__device__ __half g_xlo[MROWS*DM];
__device__ __half g_wth[4*DM*DM];    // W^T hi (scaled x32): [w][n][k]
__device__ __half g_wtl[4*DM*DM];    // W^T lo

// ======================= mma / ldmatrix / cp.async helpers ==================
__device__ __forceinline__ void mma_f32(float acc[4], const uint32_t a[4],
                                        const uint32_t b[2]) {
    asm volatile(
        "mma.sync.aligned.m16n8k16.row.col.f32.f16.f16.f32 "
        "{%0,%1,%2,%3}, {%4,%5,%6,%7}, {%8,%9}, {%0,%1,%2,%3};"
        : "+f"(acc[0]), "+f"(acc[1]), "+f"(acc[2]), "+f"(acc[3])
        : "r"(a[0]), "r"(a[1]), "r"(a[2]), "r"(a[3]), "r"(b[0]), "r"(b[1]));
}
__device__ __forceinline__ void mma_f16(uint32_t c[2], const uint32_t a[4],
                                        const uint32_t b[2]) {
    asm volatile(
        "mma.sync.aligned.m16n8k16.row.col.f16.f16.f16.f16 "
        "{%0,%1}, {%2,%3,%4,%5}, {%6,%7}, {%0,%1};"
        : "+r"(c[0]), "+r"(c[1])
        : "r"(a[0]), "r"(a[1]), "r"(a[2]), "r"(a[3]), "r"(b[0]), "r"(b[1]));
}
__device__ __forceinline__ void merge_f16(float acc[4], const uint32_t c[2]) {
    __half2 h0 = *(const __half2*)&c[0];
    __half2 h1 = *(const __half2*)&c[1];
    acc[0] += __low2float(h0); acc[1] += __high2float(h0);
    acc[2] += __low2float(h1); acc[3] += __high2float(h1);
}
#define LDSM_X4(R0, R1, R2, R3, A) \
    asm volatile("ldmatrix.sync.aligned.m8n8.x4.shared.b16 {%0,%1,%2,%3}, [%4];" \
        : "=r"(R0), "=r"(R1), "=r"(R2), "=r"(R3) : "r"(A))
__device__ __forceinline__ uint32_t smem_u32(const void* p) {
    uint32_t a;
    asm("{ .reg .u64 t; cvta.to.shared.u64 t, %1; cvt.u32.u64 %0, t; }"
        : "=r"(a) : "l"(p));
    return a;
}
#define CP16(dst, src) \
    asm volatile("cp.async.cg.shared.global [%0], [%1], 16;" \
        :: "r"(dst), "l"(src))
#define CP_COMMIT() asm volatile("cp.async.commit_group;")
#define CP_WAIT(n)  asm volatile("cp.async.wait_group %0;" :: "n"(n))

__device__ __forceinline__ void pack_hilo(float a, float b,
                                          uint32_t& hi, uint32_t& lo) {
    __half ha = __float2half_rn(a);
    __half hb = __float2half_rn(b);
    __half2 H = __halves2half2(ha, hb);
    hi = *(uint32_t*)&H;
    __half2 L = __floats2half2_rn(a - __half2float(ha), b - __half2float(hb));
    lo = *(uint32_t*)&L;
}

// ---------------- relative-position bias precompute -------------------------
__global__ void bias_kernel(const float* __restrict__ table) {
    int idx = blockIdx.x * blockDim.x + threadIdx.x;
    if (idx >= RELN) return;
    int rel = idx - (SEQ - 1);
    int bucket = (rel > 0) ? 16 : 0;
    int rabs = rel < 0 ? -rel : rel;
    int add;
    if (rabs < 8) {
        add = rabs;
    } else {
        double lf = log((double)rabs / 8.0) / log(16.0) * 8.0;
        add = 8 + (int)lf;
        if (add > 15) add = 15;
    }
    bucket += add;
#pragma unroll
    for (int h = 0; h < NH; h++)
        g_bias[h * RELN + idx] = table[bucket * NH + h];
}

// ---------------- fp32 X -> (hi,lo) fp16 split -------------------------------
__global__ __launch_bounds__(256) void xcvt(const float* __restrict__ in,
                                            int n4) {
    int i = blockIdx.x * blockDim.x + threadIdx.x;
    if (i >= n4) return;
    float4 x = ((const float4*)in)[i];
    uint32_t h0, l0, h1, l1;
    pack_hilo(x.x, x.y, h0, l0);
    pack_hilo(x.z, x.w, h1, l1);
    *(uint2*)&g_xhi[i * 4] = make_uint2(h0, h1);
    *(uint2*)&g_xlo[i * 4] = make_uint2(l0, l1);
}

// ---------------- W [K][N] -> W^T (hi,lo) fp16 x32 [N][K] -------------------
__global__ __launch_bounds__(256) void wt_cvt(const float* __restrict__ Wq,
                                              const float* __restrict__ Wk,
                                              const float* __restrict__ Wv,
                                              const float* __restrict__ Wo) {
    __shared__ float tile[32][33];
    int w = blockIdx.z;
    const float* W = (w == 0) ? Wq : (w == 1) ? Wk : (w == 2) ? Wv : Wo;
    int kb = blockIdx.y * 32, nb = blockIdx.x * 32;
    int tx = threadIdx.x, ty = threadIdx.y;
    for (int r = ty; r < 32; r += 8)
        tile[r][tx] = W[(size_t)(kb + r) * DM + nb + tx];
    __syncthreads();
    __half* oh = g_wth + (size_t)w * DM * DM;
    __half* ol = g_wtl + (size_t)w * DM * DM;
    for (int r = ty; r < 32; r += 8) {
        float x = tile[tx][r] * WSCALE;
        __half h = __float2half_rn(x);
        __half l = __float2half_rn(x - __half2float(h));
        size_t o = (size_t)(nb + r) * DM + kb + tx;
        oh[o] = h;
        ol[o] = l;
    }
}

// ---------------- split-fp16 GEMM, one-barrier cp.async pipeline ------------
#define AW       2560
#define RSTRIDE  20
#define SLOT_W   (4*AW)
#define GEMM_SMEM_BYTES (2*SLOT_W*4)   // 81920
#define VPAD 133

__global__ __launch_bounds__(256) void gemm_mma(
    int wbase, int mode, float* __restrict__ outp)
{
    extern __shared__ __align__(16) uint32_t gsm[];

    const int tid = threadIdx.x;
    const int wid = tid >> 5, lane = tid & 31;
    const int wm = wid & 1;
    const int wn = wid >> 1;
    const int fr = lane >> 2;
    const int fc = lane & 3;
    const int arow_l = (lane & 7) + ((lane >> 3) & 1) * 8;
    const int acol_l = (lane >> 4) * 4;
    const int brow_l = (lane & 7) + (lane >> 4) * 8;
    const int bcol_l = ((lane >> 3) & 1) * 4;

    const int w  = wbase + blockIdx.z;
    const int m0 = blockIdx.y * 128;
    const int n0 = blockIdx.x * 128;
    const __half* __restrict__ ah = g_xhi;
    const __half* __restrict__ al = g_xlo;
    const __half* __restrict__ bh = g_wth + (size_t)w * DM * DM;
    const __half* __restrict__ bl = g_wtl + (size_t)w * DM * DM;

    const __half* asrc[4];
    const __half* bsrc[4];
    uint32_t adst[4], bdst[4];
    const uint32_t sb0 = smem_u32(gsm);
#pragma unroll
    for (int i = 0; i < 4; i++) {
        int idx = tid + i * 256;
        int sel = idx >> 9, r = (idx >> 2) & 127, j = idx & 3;
        asrc[i] = (sel ? al : ah) + (size_t)(m0 + r) * DM + j * 8;
        adst[i] = sb0 + (uint32_t)(sel * AW + r * RSTRIDE + j * 4) * 4;
        bsrc[i] = (sel ? bl : bh) + (size_t)(n0 + r) * DM + j * 8;
        bdst[i] = sb0 + (uint32_t)(2 * AW + sel * AW + r * RSTRIDE + j * 4) * 4;
    }

    const int a_base_w = (wm * 64 + arow_l) * RSTRIDE + acol_l;
    const int b_base_w = (wn * 32 + brow_l) * RSTRIDE + bcol_l;

    float acc[4][4][4];
    uint32_t accL[4][4][2];
#pragma unroll
    for (int i = 0; i < 4; i++)
#pragma unroll
        for (int j = 0; j < 4; j++) {
#pragma unroll
            for (int q = 0; q < 4; q++) acc[i][j][q] = 0.f;
            accL[i][j][0] = 0u; accL[i][j][1] = 0u;
        }

    // prologue: prefetch chunk 0 into slot 0
#pragma unroll
    for (int i = 0; i < 4; i++) {
        CP16(adst[i], asrc[i]);
        CP16(bdst[i], bsrc[i]);
    }
    CP_COMMIT();

    for (int c = 0; c < 32; c++) {
        CP_WAIT(0);
        __syncthreads();

        const uint32_t sws = sb0 + (c & 1) * (SLOT_W * 4);
#pragma unroll
        for (int ks = 0; ks < 2; ks++) {
            const int kw = ks * 8;
            uint32_t Af[4][4], Bhf[4][2], Blf[4][2];
#pragma unroll
            for (int mf = 0; mf < 4; mf++) {
                uint32_t ad = sws + (uint32_t)(a_base_w + mf * 16 * RSTRIDE + kw) * 4;
                LDSM_X4(Af[mf][0], Af[mf][1], Af[mf][2], Af[mf][3], ad);
            }
#pragma unroll
            for (int j = 0; j < 2; j++) {
                uint32_t bd = sws + (uint32_t)(2 * AW + b_base_w + j * 16 * RSTRIDE + kw) * 4;
                LDSM_X4(Bhf[2 * j][0], Bhf[2 * j][1],
                        Bhf[2 * j + 1][0], Bhf[2 * j + 1][1], bd);
                LDSM_X4(Blf[2 * j][0], Blf[2 * j][1],
                        Blf[2 * j + 1][0], Blf[2 * j + 1][1], bd + AW * 4);
            }
            if (ks == 0 && c < 31) {
                const int k1 = (c + 1) * 32;
                const uint32_t so = ((c + 1) & 1) * (SLOT_W * 4);
#pragma unroll
                for (int i = 0; i < 4; i++) {
                    CP16(adst[i] + so, asrc[i] + k1);
                    CP16(bdst[i] + so, bsrc[i] + k1);
                }
                CP_COMMIT();
            }
#pragma unroll
            for (int mf = 0; mf < 4; mf++)
#pragma unroll
                for (int nf = 0; nf < 4; nf++)
                    mma_f32(acc[mf][nf], Af[mf], Bhf[nf]);    // hi*hi (f32)
#pragma unroll
            for (int mf = 0; mf < 4; mf++)
#pragma unroll
                for (int nf = 0; nf < 4; nf++)
                    mma_f16(accL[mf][nf], Af[mf], Blf[nf]);   // hi*lo (f16)
#pragma unroll
            for (int mf = 0; mf < 4; mf++) {
                uint32_t ad = sws + (uint32_t)(AW + a_base_w + mf * 16 * RSTRIDE + kw) * 4;
                LDSM_X4(Af[mf][0], Af[mf][1], Af[mf][2], Af[mf][3], ad);
            }
#pragma unroll
            for (int mf = 0; mf < 4; mf++)
#pragma unroll
                for (int nf = 0; nf < 4; nf++)
                    mma_f16(accL[mf][nf], Af[mf], Bhf[nf]);   // lo*hi (f16)
        }
    }

    // merge f16 accumulators + apply 1/32 W scale
#pragma unroll
    for (int mf = 0; mf < 4; mf++)
#pragma unroll
        for (int nf = 0; nf < 4; nf++) {
            merge_f16(acc[mf][nf], accL[mf][nf]);
#pragma unroll
            for (int q = 0; q < 4; q++) acc[mf][nf][q] *= INVWS;
        }

    // ---- epilogue ----
    if (mode == 0 && w == 2) {
        __syncthreads();
        float* SMF = (float*)gsm;              // [128][VPAD]
#pragma unroll
        for (int mf = 0; mf < 4; mf++) {
            int rl = wm * 64 + mf * 16 + fr;
#pragma unroll
            for (int nf = 0; nf < 4; nf++) {
                int nl = wn * 32 + nf * 8 + fc * 2;
                SMF[rl * VPAD + nl]           = acc[mf][nf][0];
                SMF[rl * VPAD + nl + 1]       = acc[mf][nf][1];
                SMF[(rl + 8) * VPAD + nl]     = acc[mf][nf][2];
                SMF[(rl + 8) * VPAD + nl + 1] = acc[mf][nf][3];
            }
        }
        __syncthreads();
        const int b = m0 >> 11, s0 = m0 & (SEQ - 1);
#pragma unroll
        for (int i = 0; i < 32; i++) {
            int idx = tid + i * 256;
            int hh = idx >> 12, rem = idx & 4095;
            int d = rem >> 6, u = rem & 63;
            float v0 = SMF[(2 * u) * VPAD + hh * 64 + d];
            float v1 = SMF[(2 * u + 1) * VPAD + hh * 64 + d];
            uint32_t hw, lw;
            pack_hilo(v0, v1, hw, lw);
            int h = blockIdx.x * 2 + hh;
            size_t o = ((size_t)(b * NH + h) * DK + d) * (SEQ / 2) + (s0 >> 1) + u;
            g_vthi[o] = hw;
            g_vtlo[o] = lw;
        }
        return;
    }
#pragma unroll
    for (int mf = 0; mf < 4; mf++) {
        int row = m0 + wm * 64 + mf * 16 + fr;
#pragma unroll
        for (int nf = 0; nf < 4; nf++) {
            int n = n0 + wn * 32 + nf * 8 + fc * 2;
            if (mode == 0) {
                int h = n >> 6, d = n & 63;
                int b = row >> 11, s = row & (SEQ - 1);
                size_t wi = ((size_t)(b * NH + h) * SEQ + s) * (DK / 2) + (d >> 1);
                uint32_t* dsth = (w == 0) ? g_qhi_w : g_khi_w;
                uint32_t* dstl = (w == 0) ? g_qlo_w : g_klo_w;
                uint32_t hw, lw;
                pack_hilo(acc[mf][nf][0], acc[mf][nf][1], hw, lw);
                dsth[wi] = hw; dstl[wi] = lw;
                pack_hilo(acc[mf][nf][2], acc[mf][nf][3], hw, lw);
                dsth[wi + 8 * (DK / 2)] = hw;
                dstl[wi + 8 * (DK / 2)] = lw;
            } else {
                *(float2*)(outp + (size_t)row * DM + n) =
                    make_float2(acc[mf][nf][0], acc[mf][nf][1]);
                *(float2*)(outp + (size_t)(row + 8) * DM + n) =
                    make_float2(acc[mf][nf][2], acc[mf][nf][3]);
            }
        }
    }
}

// ---------------- flash attention, one-barrier cp.async pipeline ------------
#define KSTR 36
#define VSTR 68
#define S_KH 0
#define S_KL (128*KSTR)
#define S_VH (2*128*KSTR)
#define S_VL (S_VH + 64*VSTR)
#define S_SB (S_VH + 2*64*VSTR)
#define SLOT3_W (S_SB + 256)
#define ATTN3_BYTES (2*SLOT3_W*4)   // 145408

__global__ __launch_bounds__(256, 1) void attn_mma() {
    extern __shared__ __align__(16) uint32_t SW3[];

    const int bh = blockIdx.y;
    const int h = bh & (NH - 1);
    const int b = bh >> 4;
    const int q0 = blockIdx.x * 128;
    const int tid = threadIdx.x;
    const int wid = tid >> 5, lane = tid & 31;
    const int fr = lane >> 2, fc = lane & 3;
    const int brow_l = (lane & 7) + (lane >> 4) * 8;
    const int bcol_l = ((lane >> 3) & 1) * 4;

    const size_t kwbase = (size_t)bh * SEQ * (DK / 2);
    const size_t vwbase = (size_t)bh * DK * (SEQ / 2);
    const uint32_t sb0 = smem_u32(SW3);

    uint32_t Qh[4][4], Ql[4][4];
    {
        const size_t qb = kwbase + (size_t)(q0 + 16 * wid + fr) * (DK / 2);
#pragma unroll
        for (int ks = 0; ks < 4; ks++) {
            size_t i0 = qb + ks * 8 + fc;
            Qh[ks][0] = g_qhi_w[i0];
            Qh[ks][1] = g_qhi_w[i0 + 8 * (DK / 2)];
            Qh[ks][2] = g_qhi_w[i0 + 4];
            Qh[ks][3] = g_qhi_w[i0 + 8 * (DK / 2) + 4];
            Ql[ks][0] = g_qlo_w[i0];
            Ql[ks][1] = g_qlo_w[i0 + 8 * (DK / 2)];
            Ql[ks][2] = g_qlo_w[i0 + 4];
            Ql[ks][3] = g_qlo_w[i0 + 8 * (DK / 2) + 4];
        }
    }

    float Oa[8][4];
#pragma unroll
    for (int i = 0; i < 8; i++)
#pragma unroll
        for (int q = 0; q < 4; q++) Oa[i][q] = 0.f;
    float m_a = -1e30f, m_b = -1e30f, l_a = 0.f, l_b = 0.f;

    const int sboff = 2 * fc - 16 * wid - fr + 128;

    auto prefetch = [&](int t) {
        const int slot = t & 1;
        const uint32_t sbase = sb0 + slot * SLOT3_W * 4;
        const int k0 = t * 128;
#pragma unroll
        for (int i = 0; i < 4; i++) {
            int idx = tid + i * 256;
            int r = idx >> 3, jc = idx & 7;
            size_t src = kwbase + (size_t)(k0 + r) * (DK / 2) + jc * 4;
            uint32_t doff = (uint32_t)(r * KSTR + jc * 4) * 4;
            CP16(sbase + S_KH * 4 + doff, g_khi_w + src);
            CP16(sbase + S_KL * 4 + doff, g_klo_w + src);
        }
#pragma unroll
        for (int i = 0; i < 4; i++) {
            int idx = tid + i * 256;
            int d = idx >> 4, jc = idx & 15;
            size_t src = vwbase + (size_t)d * (SEQ / 2) + (k0 >> 1) + jc * 4;
            uint32_t doff = (uint32_t)(d * VSTR + jc * 4) * 4;
            CP16(sbase + S_VH * 4 + doff, g_vthi + src);
            CP16(sbase + S_VL * 4 + doff, g_vtlo + src);
        }
        {
            int gi = 2047 + k0 - q0 + tid - 128;
            gi = gi < 0 ? 0 : (gi > RELN - 1 ? RELN - 1 : gi);
            float bv = g_bias[h * RELN + gi];
            SW3[slot * SLOT3_W + S_SB + tid] = __float_as_uint(bv);
        }
    };

    prefetch(0);
    CP_COMMIT();

    for (int t = 0; t < SEQ / 128; t++) {
        CP_WAIT(0);
        __syncthreads();
        if (t < SEQ / 128 - 1) {
            prefetch(t + 1);
            CP_COMMIT();
        }

        const uint32_t sws = sb0 + (t & 1) * SLOT3_W * 4;
        const float* Sb = (const float*)(SW3 + (t & 1) * SLOT3_W + S_SB);

        // ---- phase 1: S = Q K^T ----
        float sc[16][4];
        uint32_t scL[16][2];
#pragma unroll
        for (int nf = 0; nf < 16; nf++) {
#pragma unroll
            for (int q = 0; q < 4; q++) sc[nf][q] = 0.f;
            scL[nf][0] = 0u; scL[nf][1] = 0u;
        }

#pragma unroll
        for (int ks = 0; ks < 4; ks++) {
            const int kw = ks * 8 + bcol_l;
#pragma unroll
            for (int j = 0; j < 8; j++) {
                uint32_t kd = sws + (uint32_t)(S_KH + (j * 16 + brow_l) * KSTR + kw) * 4;
                uint32_t bf0[2], bf1[2];
                LDSM_X4(bf0[0], bf0[1], bf1[0], bf1[1], kd);
                mma_f32(sc[2 * j],     Qh[ks], bf0);
                mma_f32(sc[2 * j + 1], Qh[ks], bf1);
                mma_f16(scL[2 * j],     Ql[ks], bf0);
                mma_f16(scL[2 * j + 1], Ql[ks], bf1);
                LDSM_X4(bf0[0], bf0[1], bf1[0], bf1[1],
                        kd + (S_KL - S_KH) * 4);
                mma_f16(scL[2 * j],     Qh[ks], bf0);
                mma_f16(scL[2 * j + 1], Qh[ks], bf1);
            }
        }
#pragma unroll
        for (int nf = 0; nf < 16; nf++)
            merge_f16(sc[nf], scL[nf]);

        // ---- bias add ----
        float pb0 = Sb[sboff - 8], pb1 = Sb[sboff - 7];
#pragma unroll
        for (int nf = 0; nf < 16; nf++) {
            float b0 = Sb[sboff + 8 * nf];
            float b1 = Sb[sboff + 8 * nf + 1];
            sc[nf][0] += b0;
            sc[nf][1] += b1;
            sc[nf][2] += pb0;
            sc[nf][3] += pb1;
            pb0 = b0; pb1 = b1;
        }

        // ---- online softmax ----
        float mxa = -1e30f, mxb = -1e30f;
#pragma unroll
        for (int nf = 0; nf < 16; nf++) {
            mxa = fmaxf(mxa, fmaxf(sc[nf][0], sc[nf][1]));
            mxb = fmaxf(mxb, fmaxf(sc[nf][2], sc[nf][3]));
        }
        mxa = fmaxf(mxa, __shfl_xor_sync(0xffffffffu, mxa, 1));
        mxa = fmaxf(mxa, __shfl_xor_sync(0xffffffffu, mxa, 2));
        mxb = fmaxf(mxb, __shfl_xor_sync(0xffffffffu, mxb, 1));
        mxb = fmaxf(mxb, __shfl_xor_sync(0xffffffffu, mxb, 2));
        float mna = fmaxf(m_a, mxa), mnb = fmaxf(m_b, mxb);
        float ca = __expf(m_a - mna), cb = __expf(m_b - mnb);
        float sa = 0.f, sb2 = 0.f;
#pragma unroll
        for (int nf = 0; nf < 16; nf++) {
            sc[nf][0] = __expf(sc[nf][0] - mna);
            sc[nf][1] = __expf(sc[nf][1] - mna);
            sc[nf][2] = __expf(sc[nf][2] - mnb);
            sc[nf][3] = __expf(sc[nf][3] - mnb);
            sa  += sc[nf][0] + sc[nf][1];
            sb2 += sc[nf][2] + sc[nf][3];
        }
        sa  += __shfl_xor_sync(0xffffffffu, sa, 1);
        sa  += __shfl_xor_sync(0xffffffffu, sa, 2);
        sb2 += __shfl_xor_sync(0xffffffffu, sb2, 1);
        sb2 += __shfl_xor_sync(0xffffffffu, sb2, 2);
        l_a = l_a * ca + sa;
        l_b = l_b * cb + sb2;
        m_a = mna; m_b = mnb;

#pragma unroll
        for (int i = 0; i < 8; i++) {
            Oa[i][0] *= ca; Oa[i][1] *= ca;
            Oa[i][2] *= cb; Oa[i][3] *= cb;
        }

        // ---- phase 2: O += P V ----
        uint32_t OL[8][2];
#pragma unroll
        for (int i = 0; i < 8; i++) { OL[i][0] = 0u; OL[i][1] = 0u; }
#pragma unroll
        for (int ks2 = 0; ks2 < 8; ks2++) {
            uint32_t Ph[4], Pl[4];
            pack_hilo(sc[2*ks2][0],   sc[2*ks2][1],   Ph[0], Pl[0]);
            pack_hilo(sc[2*ks2][2],   sc[2*ks2][3],   Ph[1], Pl[1]);
            pack_hilo(sc[2*ks2+1][0], sc[2*ks2+1][1], Ph[2], Pl[2]);
            pack_hilo(sc[2*ks2+1][2], sc[2*ks2+1][3], Ph[3], Pl[3]);
            const int kw2 = ks2 * 8 + bcol_l;
#pragma unroll
            for (int j = 0; j < 4; j++) {
                uint32_t vd = sws + (uint32_t)(S_VH + (j * 16 + brow_l) * VSTR + kw2) * 4;
                uint32_t bf0[2], bf1[2];
                LDSM_X4(bf0[0], bf0[1], bf1[0], bf1[1], vd);
                mma_f32(Oa[2 * j],     Ph, bf0);
                mma_f32(Oa[2 * j + 1], Ph, bf1);
                mma_f16(OL[2 * j],     Pl, bf0);
                mma_f16(OL[2 * j + 1], Pl, bf1);
                LDSM_X4(bf0[0], bf0[1], bf1[0], bf1[1],
                        vd + (S_VL - S_VH) * 4);
                mma_f16(OL[2 * j],     Ph, bf0);
                mma_f16(OL[2 * j + 1], Ph, bf1);
            }
        }
#pragma unroll
        for (int i = 0; i < 8; i++)
            merge_f16(Oa[i], OL[i]);
    }

    // ---- epilogue: write hi/lo fp16 straight into g_xhi/g_xlo --------------
    float inva = 1.0f / l_a, invb = 1.0f / l_b;
    int ra = q0 + 16 * wid + fr;
#pragma unroll
    for (int nf2 = 0; nf2 < 8; nf2++) {
        int d = nf2 * 8 + 2 * fc;
        size_t ia = (size_t)(b * SEQ + ra) * DM + h * DK + d;
        size_t ib = ia + (size_t)8 * DM;
        uint32_t hw, lw;
        pack_hilo(Oa[nf2][0] * inva, Oa[nf2][1] * inva, hw, lw);
        *(uint32_t*)&g_xhi[ia] = hw;
        *(uint32_t*)&g_xlo[ia] = lw;
        pack_hilo(Oa[nf2][2] * invb, Oa[nf2][3] * invb, hw, lw);
        *(uint32_t*)&g_xhi[ib] = hw;
        *(uint32_t*)&g_xlo[ib] = lw;
    }
}

// ---------------- launch ----------------------------------------------------
extern "C" void kernel_launch(void* const* d_in, const int* in_sizes, int n_in,
                              void* d_out, int out_size) {
    const float* X   = (const float*)d_in[0];
    const float* Wq  = (const float*)d_in[1];
    const float* Wk  = (const float*)d_in[2];
    const float* Wv  = (const float*)d_in[3];
    const float* Wo  = (const float*)d_in[4];
    const float* tbl = (const float*)d_in[5];
    float* out = (float*)d_out;

    cudaFuncSetAttribute(attn_mma,
                         cudaFuncAttributeMaxDynamicSharedMemorySize,
                         ATTN3_BYTES);
    cudaFuncSetAttribute(gemm_mma,
                         cudaFuncAttributeMaxDynamicSharedMemorySize,
                         GEMM_SMEM_BYTES);

    bias_kernel<<<(RELN + 255) / 256, 256>>>(tbl);

    xcvt<<<(MROWS * DM / 4 + 255) / 256, 256>>>(X, MROWS * DM / 4);
    dim3 gw(DM / 32, DM / 32, 4);
    wt_cvt<<<gw, dim3(32, 8)>>>(Wq, Wk, Wv, Wo);

    dim3 g1(DM / 128, MROWS / 128, 3);
    gemm_mma<<<g1, 256, GEMM_SMEM_BYTES>>>(0, 0, nullptr);

    dim3 g2(SEQ / 128, BSZ * NH);
    attn_mma<<<g2, 256, ATTN3_BYTES>>>();

    dim3 g3(DM / 128, MROWS / 128, 1);
    gemm_mma<<<g3, 256, GEMM_SMEM_BYTES>>>(3, 1, out);
}

// round 14
// speedup vs baseline: 1.1981x; 1.1981x over previous
#include <cuda_runtime.h>
#include <cuda_bf16.h>
#include <cuda_fp16.h>
#include <math.h>
#include <stdint.h>

#define BSZ   2
#define SEQ   2048
#define DM    1024
#define NH    16
#define DK    64
#define RELN  (2*SEQ-1)   // 4095
#define MROWS (BSZ*SEQ)   // 4096

// ---------------- scratch (device globals; device-code access only) --------
__device__ float g_bias[NH*RELN];            // [h][rel + S-1]

__device__ uint32_t g_qhi_w[BSZ*NH*SEQ*(DK/2)];   // Q packed bf16 hi words
__device__ uint32_t g_qlo_w[BSZ*NH*SEQ*(DK/2)];
__device__ uint32_t g_khi_w[BSZ*NH*SEQ*(DK/2)];   // K packed bf16 words
__device__ uint32_t g_klo_w[BSZ*NH*SEQ*(DK/2)];
__device__ uint32_t g_vthi[BSZ*NH*DK*(SEQ/2)];    // V^T fp16 words [bh][d][u]
__device__ uint32_t g_vtlo[BSZ*NH*DK*(SEQ/2)];

__device__ __nv_bfloat16 g_xhi[MROWS*DM];   // activations hi/lo (bf16)
__device__ __nv_bfloat16 g_xlo[MROWS*DM];
__device__ __nv_bfloat16 g_wth[4*DM*DM];    // W^T hi: [w][n][k]
__device__ __nv_bfloat16 g_wtl[4*DM*DM];    // W^T lo

// ======================= mma / ldmatrix / cp.async helpers ==================
__device__ __forceinline__ void mma_bf16(float acc[4], const uint32_t a[4],
                                         const uint32_t b[2]) {
    asm volatile(
        "mma.sync.aligned.m16n8k16.row.col.f32.bf16.bf16.f32 "
        "{%0,%1,%2,%3}, {%4,%5,%6,%7}, {%8,%9}, {%0,%1,%2,%3};"
        : "+f"(acc[0]), "+f"(acc[1]), "+f"(acc[2]), "+f"(acc[3])
        : "r"(a[0]), "r"(a[1]), "r"(a[2]), "r"(a[3]), "r"(b[0]), "r"(b[1]));
}
__device__ __forceinline__ void mma_f16f32(float acc[4], const uint32_t a[4],
                                           const uint32_t b[2]) {
    asm volatile(
        "mma.sync.aligned.m16n8k16.row.col.f32.f16.f16.f32 "
        "{%0,%1,%2,%3}, {%4,%5,%6,%7}, {%8,%9}, {%0,%1,%2,%3};"
        : "+f"(acc[0]), "+f"(acc[1]), "+f"(acc[2]), "+f"(acc[3])
        : "r"(a[0]), "r"(a[1]), "r"(a[2]), "r"(a[3]), "r"(b[0]), "r"(b[1]));
}
#define LDSM_X4(R0, R1, R2, R3, A) \
    asm volatile("ldmatrix.sync.aligned.m8n8.x4.shared.b16 {%0,%1,%2,%3}, [%4];" \
        : "=r"(R0), "=r"(R1), "=r"(R2), "=r"(R3) : "r"(A))
__device__ __forceinline__ uint32_t smem_u32(const void* p) {
    uint32_t a;
    asm("{ .reg .u64 t; cvta.to.shared.u64 t, %1; cvt.u32.u64 %0, t; }"
        : "=r"(a) : "l"(p));
    return a;
}
#define CP16(dst, src) \
    asm volatile("cp.async.cg.shared.global [%0], [%1], 16;" \
        :: "r"(dst), "l"(src))
#define CP_COMMIT() asm volatile("cp.async.commit_group;")
#define CP_WAIT(n)  asm volatile("cp.async.wait_group %0;" :: "n"(n))

__device__ __forceinline__ uint32_t packbf(float a, float b) {
    __nv_bfloat162 t;
    t.x = __float2bfloat16_rn(a);
    t.y = __float2bfloat16_rn(b);
    return *(uint32_t*)&t;
}
__device__ __forceinline__ void pack_hilo(float a, float b,
                                          uint32_t& hi, uint32_t& lo) {
    __nv_bfloat16 ha = __float2bfloat16_rn(a);
    __nv_bfloat16 hb = __float2bfloat16_rn(b);
    __nv_bfloat162 th; th.x = ha; th.y = hb;
    hi = *(uint32_t*)&th;
    lo = packbf(a - __bfloat162float(ha), b - __bfloat162float(hb));
}
__device__ __forceinline__ uint32_t packf16(float a, float b) {
    __half2 t = __floats2half2_rn(a, b);
    return *(uint32_t*)&t;
}
__device__ __forceinline__ void pack_hilo_f16(float a, float b,
                                              uint32_t& hi, uint32_t& lo) {
    __half ha = __float2half_rn(a);
    __half hb = __float2half_rn(b);
    __half2 H = __halves2half2(ha, hb);
    hi = *(uint32_t*)&H;
    lo = packf16(a - __half2float(ha), b - __half2float(hb));
}

// ---------------- relative-position bias precompute -------------------------
__global__ void bias_kernel(const float* __restrict__ table) {
    int idx = blockIdx.x * blockDim.x + threadIdx.x;
    if (idx >= RELN) return;
    int rel = idx - (SEQ - 1);
    int bucket = (rel > 0) ? 16 : 0;
    int rabs = rel < 0 ? -rel : rel;
    int add;
    if (rabs < 8) {
        add = rabs;
    } else {
        double lf = log((double)rabs / 8.0) / log(16.0) * 8.0;
        add = 8 + (int)lf;
        if (add > 15) add = 15;
    }
    bucket += add;
#pragma unroll
    for (int h = 0; h < NH; h++)
        g_bias[h * RELN + idx] = table[bucket * NH + h];
}

// ---------------- fp32 X -> (hi,lo) bf16 split -------------------------------
__global__ __launch_bounds__(256) void xcvt(const float* __restrict__ in,
                                            int n4) {
    int i = blockIdx.x * blockDim.x + threadIdx.x;
    if (i >= n4) return;
    float4 x = ((const float4*)in)[i];
    float xs[4] = {x.x, x.y, x.z, x.w};
    __nv_bfloat16 hb[4], lb[4];
#pragma unroll
    for (int j = 0; j < 4; j++) {
        hb[j] = __float2bfloat16_rn(xs[j]);
        lb[j] = __float2bfloat16_rn(xs[j] - __bfloat162float(hb[j]));
    }
    *(uint2*)&g_xhi[i * 4] = *(uint2*)hb;
    *(uint2*)&g_xlo[i * 4] = *(uint2*)lb;
}

// ---------------- W [K][N] -> W^T (hi,lo) bf16 [N][K] -----------------------
__global__ __launch_bounds__(256) void wt_cvt(const float* __restrict__ Wq,
                                              const float* __restrict__ Wk,
                                              const float* __restrict__ Wv,
                                              const float* __restrict__ Wo) {
    __shared__ float tile[32][33];
    int w = blockIdx.z;
    const float* W = (w == 0) ? Wq : (w == 1) ? Wk : (w == 2) ? Wv : Wo;
    int kb = blockIdx.y * 32, nb = blockIdx.x * 32;
    int tx = threadIdx.x, ty = threadIdx.y;
    for (int r = ty; r < 32; r += 8)
        tile[r][tx] = W[(size_t)(kb + r) * DM + nb + tx];
    __syncthreads();
    __nv_bfloat16* oh = g_wth + (size_t)w * DM * DM;
    __nv_bfloat16* ol = g_wtl + (size_t)w * DM * DM;
    for (int r = ty; r < 32; r += 8) {
        float x = tile[tx][r];
        __nv_bfloat16 h = __float2bfloat16_rn(x);
        __nv_bfloat16 l = __float2bfloat16_rn(x - __bfloat162float(h));
        size_t o = (size_t)(nb + r) * DM + kb + tx;
        oh[o] = h;
        ol[o] = l;
    }
}

// ---------------- split-bf16 GEMM, one-barrier cp.async pipeline ------------
#define AW       2560
#define RSTRIDE  20
#define SLOT_W   (4*AW)
#define GEMM_SMEM_BYTES (2*SLOT_W*4)   // 81920
#define VPAD 133

__global__ __launch_bounds__(256, 2) void gemm_mma(
    int wbase, int mode, float* __restrict__ outp)
{
    extern __shared__ __align__(16) uint32_t gsm[];

    const int tid = threadIdx.x;
    const int wid = tid >> 5, lane = tid & 31;
    const int wm = wid & 1;
    const int wn = wid >> 1;
    const int fr = lane >> 2;
    const int fc = lane & 3;
    const int arow_l = (lane & 7) + ((lane >> 3) & 1) * 8;
    const int acol_l = (lane >> 4) * 4;
    const int brow_l = (lane & 7) + (lane >> 4) * 8;
    const int bcol_l = ((lane >> 3) & 1) * 4;

    const int w  = wbase + blockIdx.z;
    const int m0 = blockIdx.y * 128;
    const int n0 = blockIdx.x * 128;
    const __nv_bfloat16* __restrict__ ah = g_xhi;
    const __nv_bfloat16* __restrict__ al = g_xlo;
    const __nv_bfloat16* __restrict__ bh = g_wth + (size_t)w * DM * DM;
    const __nv_bfloat16* __restrict__ bl = g_wtl + (size_t)w * DM * DM;

    const __nv_bfloat16* asrc[4];
    const __nv_bfloat16* bsrc[4];
    uint32_t adst[4], bdst[4];
    const uint32_t sb0 = smem_u32(gsm);
#pragma unroll
    for (int i = 0; i < 4; i++) {
        int idx = tid + i * 256;
        int sel = idx >> 9, r = (idx >> 2) & 127, j = idx & 3;
        asrc[i] = (sel ? al : ah) + (size_t)(m0 + r) * DM + j * 8;
        adst[i] = sb0 + (uint32_t)(sel * AW + r * RSTRIDE + j * 4) * 4;
        bsrc[i] = (sel ? bl : bh) + (size_t)(n0 + r) * DM + j * 8;
        bdst[i] = sb0 + (uint32_t)(2 * AW + sel * AW + r * RSTRIDE + j * 4) * 4;
    }

    const int a_base_w = (wm * 64 + arow_l) * RSTRIDE + acol_l;
    const int b_base_w = (wn * 32 + brow_l) * RSTRIDE + bcol_l;

    float acc[4][4][4];
#pragma unroll
    for (int i = 0; i < 4; i++)
#pragma unroll
        for (int j = 0; j < 4; j++)
#pragma unroll
            for (int q = 0; q < 4; q++) acc[i][j][q] = 0.f;

    // prologue: prefetch chunk 0 into slot 0
#pragma unroll
    for (int i = 0; i < 4; i++) {
        CP16(adst[i], asrc[i]);
        CP16(bdst[i], bsrc[i]);
    }
    CP_COMMIT();

    for (int c = 0; c < 32; c++) {
        CP_WAIT(0);          // chunk c landed
        __syncthreads();     // visible to all; other slot fully consumed

        const uint32_t sws = sb0 + (c & 1) * (SLOT_W * 4);
#pragma unroll
        for (int ks = 0; ks < 2; ks++) {
            const int kw = ks * 8;
            uint32_t Af[4][4], Bhf[4][2], Blf[4][2];
#pragma unroll
            for (int mf = 0; mf < 4; mf++) {
                uint32_t ad = sws + (uint32_t)(a_base_w + mf * 16 * RSTRIDE + kw) * 4;
                LDSM_X4(Af[mf][0], Af[mf][1], Af[mf][2], Af[mf][3], ad);
            }
#pragma unroll
            for (int j = 0; j < 2; j++) {
                uint32_t bd = sws + (uint32_t)(2 * AW + b_base_w + j * 16 * RSTRIDE + kw) * 4;
                LDSM_X4(Bhf[2 * j][0], Bhf[2 * j][1],
                        Bhf[2 * j + 1][0], Bhf[2 * j + 1][1], bd);
                LDSM_X4(Blf[2 * j][0], Blf[2 * j][1],
                        Blf[2 * j + 1][0], Blf[2 * j + 1][1], bd + AW * 4);
            }
            if (ks == 0 && c < 31) {
                const int k1 = (c + 1) * 32;
                const uint32_t so = ((c + 1) & 1) * (SLOT_W * 4);
#pragma unroll
                for (int i = 0; i < 4; i++) {
                    CP16(adst[i] + so, asrc[i] + k1);
                    CP16(bdst[i] + so, bsrc[i] + k1);
                }
                CP_COMMIT();
            }
#pragma unroll
            for (int mf = 0; mf < 4; mf++)
#pragma unroll
                for (int nf = 0; nf < 4; nf++)
                    mma_bf16(acc[mf][nf], Af[mf], Bhf[nf]);   // hi*hi
#pragma unroll
            for (int mf = 0; mf < 4; mf++)
#pragma unroll
                for (int nf = 0; nf < 4; nf++)
                    mma_bf16(acc[mf][nf], Af[mf], Blf[nf]);   // hi*lo
#pragma unroll
            for (int mf = 0; mf < 4; mf++) {
                uint32_t ad = sws + (uint32_t)(AW + a_base_w + mf * 16 * RSTRIDE + kw) * 4;
                LDSM_X4(Af[mf][0], Af[mf][1], Af[mf][2], Af[mf][3], ad);
            }
#pragma unroll
            for (int mf = 0; mf < 4; mf++)
#pragma unroll
                for (int nf = 0; nf < 4; nf++)
                    mma_bf16(acc[mf][nf], Af[mf], Bhf[nf]);   // lo*hi
        }
    }

    // ---- epilogue ----
    if (mode == 0 && w == 2) {
        // V: transpose + pack fp16 straight into g_vthi/g_vtlo via smem staging
        __syncthreads();
        float* SMF = (float*)gsm;              // [128][VPAD]
#pragma unroll
        for (int mf = 0; mf < 4; mf++) {
            int rl = wm * 64 + mf * 16 + fr;
#pragma unroll
            for (int nf = 0; nf < 4; nf++) {
                int nl = wn * 32 + nf * 8 + fc * 2;
                SMF[rl * VPAD + nl]           = acc[mf][nf][0];
                SMF[rl * VPAD + nl + 1]       = acc[mf][nf][1];
                SMF[(rl + 8) * VPAD + nl]     = acc[mf][nf][2];
                SMF[(rl + 8) * VPAD + nl + 1] = acc[mf][nf][3];
            }
        }
        __syncthreads();
        const int b = m0 >> 11, s0 = m0 & (SEQ - 1);
#pragma unroll
        for (int i = 0; i < 32; i++) {
            int idx = tid + i * 256;
            int hh = idx >> 12, rem = idx & 4095;
            int d = rem >> 6, u = rem & 63;
            float v0 = SMF[(2 * u) * VPAD + hh * 64 + d];
            float v1 = SMF[(2 * u + 1) * VPAD + hh * 64 + d];
            uint32_t hw, lw;
            pack_hilo_f16(v0, v1, hw, lw);
            int h = blockIdx.x * 2 + hh;
            size_t o = ((size_t)(b * NH + h) * DK + d) * (SEQ / 2) + (s0 >> 1) + u;
            g_vthi[o] = hw;
            g_vtlo[o] = lw;
        }
        return;
    }
#pragma unroll
    for (int mf = 0; mf < 4; mf++) {
        int row = m0 + wm * 64 + mf * 16 + fr;
#pragma unroll
        for (int nf = 0; nf < 4; nf++) {
            int n = n0 + wn * 32 + nf * 8 + fc * 2;
            if (mode == 0) {
                int h = n >> 6, d = n & 63;
                int b = row >> 11, s = row & (SEQ - 1);
                size_t wi = ((size_t)(b * NH + h) * SEQ + s) * (DK / 2) + (d >> 1);
                uint32_t* dsth = (w == 0) ? g_qhi_w : g_khi_w;
                uint32_t* dstl = (w == 0) ? g_qlo_w : g_klo_w;
                uint32_t hw, lw;
                pack_hilo(acc[mf][nf][0], acc[mf][nf][1], hw, lw);
                dsth[wi] = hw; dstl[wi] = lw;
                pack_hilo(acc[mf][nf][2], acc[mf][nf][3], hw, lw);
                dsth[wi + 8 * (DK / 2)] = hw;
                dstl[wi + 8 * (DK / 2)] = lw;
            } else {
                *(float2*)(outp + (size_t)row * DM + n) =
                    make_float2(acc[mf][nf][0], acc[mf][nf][1]);
                *(float2*)(outp + (size_t)(row + 8) * DM + n) =
                    make_float2(acc[mf][nf][2], acc[mf][nf][3]);
            }
        }
    }
}

// ---------------- flash attention, one-barrier cp.async pipeline ------------
#define KSTR 36
#define VSTR 68
#define S_KH 0
#define S_KL (128*KSTR)
#define S_VH (2*128*KSTR)
#define S_VL (S_VH + 64*VSTR)
#define S_SB (S_VH + 2*64*VSTR)
#define SLOT3_W (S_SB + 256)
#define ATTN3_BYTES (2*SLOT3_W*4)   // 145408

__global__ __launch_bounds__(256, 1) void attn_mma() {
    extern __shared__ __align__(16) uint32_t SW3[];

    const int bh = blockIdx.y;
    const int h = bh & (NH - 1);
    const int b = bh >> 4;
    const int q0 = blockIdx.x * 128;
    const int tid = threadIdx.x;
    const int wid = tid >> 5, lane = tid & 31;
    const int fr = lane >> 2, fc = lane & 3;
    const int brow_l = (lane & 7) + (lane >> 4) * 8;
    const int bcol_l = ((lane >> 3) & 1) * 4;

    const size_t kwbase = (size_t)bh * SEQ * (DK / 2);
    const size_t vwbase = (size_t)bh * DK * (SEQ / 2);
    const uint32_t sb0 = smem_u32(SW3);

    uint32_t Qh[4][4], Ql[4][4];
    {
        const size_t qb = kwbase + (size_t)(q0 + 16 * wid + fr) * (DK / 2);
#pragma unroll
        for (int ks = 0; ks < 4; ks++) {
            size_t i0 = qb + ks * 8 + fc;
            Qh[ks][0] = g_qhi_w[i0];
            Qh[ks][1] = g_qhi_w[i0 + 8 * (DK / 2)];
            Qh[ks][2] = g_qhi_w[i0 + 4];
            Qh[ks][3] = g_qhi_w[i0 + 8 * (DK / 2) + 4];
            Ql[ks][0] = g_qlo_w[i0];
            Ql[ks][1] = g_qlo_w[i0 + 8 * (DK / 2)];
            Ql[ks][2] = g_qlo_w[i0 + 4];
            Ql[ks][3] = g_qlo_w[i0 + 8 * (DK / 2) + 4];
        }
    }

    float Oa[8][4];
#pragma unroll
    for (int i = 0; i < 8; i++)
#pragma unroll
        for (int q = 0; q < 4; q++) Oa[i][q] = 0.f;
    float m_a = -1e30f, m_b = -1e30f, l_a = 0.f, l_b = 0.f;

    const int sboff = 2 * fc - 16 * wid - fr + 128;

    auto prefetch = [&](int t) {
        const int slot = t & 1;
        const uint32_t sbase = sb0 + slot * SLOT3_W * 4;
        const int k0 = t * 128;
#pragma unroll
        for (int i = 0; i < 4; i++) {
            int idx = tid + i * 256;
            int r = idx >> 3, jc = idx & 7;
            size_t src = kwbase + (size_t)(k0 + r) * (DK / 2) + jc * 4;
            uint32_t doff = (uint32_t)(r * KSTR + jc * 4) * 4;
            CP16(sbase + S_KH * 4 + doff, g_khi_w + src);
            CP16(sbase + S_KL * 4 + doff, g_klo_w + src);
        }
#pragma unroll
        for (int i = 0; i < 4; i++) {
            int idx = tid + i * 256;
            int d = idx >> 4, jc = idx & 15;
            size_t src = vwbase + (size_t)d * (SEQ / 2) + (k0 >> 1) + jc * 4;
            uint32_t doff = (uint32_t)(d * VSTR + jc * 4) * 4;
            CP16(sbase + S_VH * 4 + doff, g_vthi + src);
            CP16(sbase + S_VL * 4 + doff, g_vtlo + src);
        }
        {
            int gi = 2047 + k0 - q0 + tid - 128;
            gi = gi < 0 ? 0 : (gi > RELN - 1 ? RELN - 1 : gi);
            float bv = g_bias[h * RELN + gi];
            SW3[slot * SLOT3_W + S_SB + tid] = __float_as_uint(bv);
        }
    };

    prefetch(0);
    CP_COMMIT();

    for (int t = 0; t < SEQ / 128; t++) {
        CP_WAIT(0);
        __syncthreads();
        if (t < SEQ / 128 - 1) {
            prefetch(t + 1);
            CP_COMMIT();
        }

        const uint32_t sws = sb0 + (t & 1) * SLOT3_W * 4;
        const float* Sb = (const float*)(SW3 + (t & 1) * SLOT3_W + S_SB);

        // ---- phase 1: S = Q K^T (bf16 3-term split) ----
        float sc[16][4];
#pragma unroll
        for (int nf = 0; nf < 16; nf++)
#pragma unroll
            for (int q = 0; q < 4; q++) sc[nf][q] = 0.f;

#pragma unroll
        for (int ks = 0; ks < 4; ks++) {
            const int kw = ks * 8 + bcol_l;
#pragma unroll
            for (int j = 0; j < 8; j++) {
                uint32_t kd = sws + (uint32_t)(S_KH + (j * 16 + brow_l) * KSTR + kw) * 4;
                uint32_t bf0[2], bf1[2];
                LDSM_X4(bf0[0], bf0[1], bf1[0], bf1[1], kd);
                mma_bf16(sc[2 * j],     Qh[ks], bf0);
                mma_bf16(sc[2 * j + 1], Qh[ks], bf1);
                mma_bf16(sc[2 * j],     Ql[ks], bf0);
                mma_bf16(sc[2 * j + 1], Ql[ks], bf1);
                LDSM_X4(bf0[0], bf0[1], bf1[0], bf1[1],
                        kd + (S_KL - S_KH) * 4);
                mma_bf16(sc[2 * j],     Qh[ks], bf0);
                mma_bf16(sc[2 * j + 1], Qh[ks], bf1);
            }
        }

        // ---- bias add ----
        float pb0 = Sb[sboff - 8], pb1 = Sb[sboff - 7];
#pragma unroll
        for (int nf = 0; nf < 16; nf++) {
            float b0 = Sb[sboff + 8 * nf];
            float b1 = Sb[sboff + 8 * nf + 1];
            sc[nf][0] += b0;
            sc[nf][1] += b1;
            sc[nf][2] += pb0;
            sc[nf][3] += pb1;
            pb0 = b0; pb1 = b1;
        }

        // ---- online softmax ----
        float mxa = -1e30f, mxb = -1e30f;
#pragma unroll
        for (int nf = 0; nf < 16; nf++) {
            mxa = fmaxf(mxa, fmaxf(sc[nf][0], sc[nf][1]));
            mxb = fmaxf(mxb, fmaxf(sc[nf][2], sc[nf][3]));
        }
        mxa = fmaxf(mxa, __shfl_xor_sync(0xffffffffu, mxa, 1));
        mxa = fmaxf(mxa, __shfl_xor_sync(0xffffffffu, mxa, 2));
        mxb = fmaxf(mxb, __shfl_xor_sync(0xffffffffu, mxb, 1));
        mxb = fmaxf(mxb, __shfl_xor_sync(0xffffffffu, mxb, 2));
        float mna = fmaxf(m_a, mxa), mnb = fmaxf(m_b, mxb);
        float ca = __expf(m_a - mna), cb = __expf(m_b - mnb);
        float sa = 0.f, sb2 = 0.f;
#pragma unroll
        for (int nf = 0; nf < 16; nf++) {
            sc[nf][0] = __expf(sc[nf][0] - mna);
            sc[nf][1] = __expf(sc[nf][1] - mna);
            sc[nf][2] = __expf(sc[nf][2] - mnb);
            sc[nf][3] = __expf(sc[nf][3] - mnb);
            sa  += sc[nf][0] + sc[nf][1];
            sb2 += sc[nf][2] + sc[nf][3];
        }
        sa  += __shfl_xor_sync(0xffffffffu, sa, 1);
        sa  += __shfl_xor_sync(0xffffffffu, sa, 2);
        sb2 += __shfl_xor_sync(0xffffffffu, sb2, 1);
        sb2 += __shfl_xor_sync(0xffffffffu, sb2, 2);
        l_a = l_a * ca + sa;
        l_b = l_b * cb + sb2;
        m_a = mna; m_b = mnb;

#pragma unroll
        for (int i = 0; i < 8; i++) {
            Oa[i][0] *= ca; Oa[i][1] *= ca;
            Oa[i][2] *= cb; Oa[i][3] *= cb;
        }

        // ---- phase 2: O += P V (P single fp16, V fp16 hi+lo: 2 MMAs) ----
#pragma unroll
        for (int ks2 = 0; ks2 < 8; ks2++) {
            uint32_t Ph[4];
            Ph[0] = packf16(sc[2*ks2][0],   sc[2*ks2][1]);
            Ph[1] = packf16(sc[2*ks2][2],   sc[2*ks2][3]);
            Ph[2] = packf16(sc[2*ks2+1][0], sc[2*ks2+1][1]);
            Ph[3] = packf16(sc[2*ks2+1][2], sc[2*ks2+1][3]);
            const int kw2 = ks2 * 8 + bcol_l;
#pragma unroll
            for (int j = 0; j < 4; j++) {
                uint32_t vd = sws + (uint32_t)(S_VH + (j * 16 + brow_l) * VSTR + kw2) * 4;
                uint32_t bf0[2], bf1[2];
                LDSM_X4(bf0[0], bf0[1], bf1[0], bf1[1], vd);
                mma_f16f32(Oa[2 * j],     Ph, bf0);
                mma_f16f32(Oa[2 * j + 1], Ph, bf1);
                LDSM_X4(bf0[0], bf0[1], bf1[0], bf1[1],
                        vd + (S_VL - S_VH) * 4);
                mma_f16f32(Oa[2 * j],     Ph, bf0);
                mma_f16f32(Oa[2 * j + 1], Ph, bf1);
            }
        }
    }

    // ---- epilogue: write hi/lo bf16 straight into g_xhi/g_xlo --------------
    float inva = 1.0f / l_a, invb = 1.0f / l_b;
    int ra = q0 + 16 * wid + fr;
#pragma unroll
    for (int nf2 = 0; nf2 < 8; nf2++) {
        int d = nf2 * 8 + 2 * fc;
        size_t ia = (size_t)(b * SEQ + ra) * DM + h * DK + d;
        size_t ib = ia + (size_t)8 * DM;
        uint32_t hw, lw;
        pack_hilo(Oa[nf2][0] * inva, Oa[nf2][1] * inva, hw, lw);
        *(uint32_t*)&g_xhi[ia] = hw;
        *(uint32_t*)&g_xlo[ia] = lw;
        pack_hilo(Oa[nf2][2] * invb, Oa[nf2][3] * invb, hw, lw);
        *(uint32_t*)&g_xhi[ib] = hw;
        *(uint32_t*)&g_xlo[ib] = lw;
    }
}

// ---------------- launch ----------------------------------------------------
extern "C" void kernel_launch(void* const* d_in, const int* in_sizes, int n_in,
                              void* d_out, int out_size) {
    const float* X   = (const float*)d_in[0];
    const float* Wq  = (const float*)d_in[1];
    const float* Wk  = (const float*)d_in[2];
    const float* Wv  = (const float*)d_in[3];
    const float* Wo  = (const float*)d_in[4];
    const float* tbl = (const float*)d_in[5];
    float* out = (float*)d_out;

    cudaFuncSetAttribute(attn_mma,
                         cudaFuncAttributeMaxDynamicSharedMemorySize,
                         ATTN3_BYTES);
    cudaFuncSetAttribute(gemm_mma,
                         cudaFuncAttributeMaxDynamicSharedMemorySize,
                         GEMM_SMEM_BYTES);

    bias_kernel<<<(RELN + 255) / 256, 256>>>(tbl);

    xcvt<<<(MROWS * DM / 4 + 255) / 256, 256>>>(X, MROWS * DM / 4);
    dim3 gw(DM / 32, DM / 32, 4);
    wt_cvt<<<gw, dim3(32, 8)>>>(Wq, Wk, Wv, Wo);

    dim3 g1(DM / 128, MROWS / 128, 3);
    gemm_mma<<<g1, 256, GEMM_SMEM_BYTES>>>(0, 0, nullptr);

    dim3 g2(SEQ / 128, BSZ * NH);
    attn_mma<<<g2, 256, ATTN3_BYTES>>>();

    dim3 g3(DM / 128, MROWS / 128, 1);
    gemm_mma<<<g3, 256, GEMM_SMEM_BYTES>>>(3, 1, out);
}

// round 15
// speedup vs baseline: 1.2726x; 1.0622x over previous
#include <cuda_runtime.h>
#include <cuda_bf16.h>
#include <cuda_fp16.h>
#include <math.h>
#include <stdint.h>

#define BSZ   2
#define SEQ   2048
#define DM    1024
#define NH    16
#define DK    64
#define RELN  (2*SEQ-1)   // 4095
#define MROWS (BSZ*SEQ)   // 4096

// ---------------- scratch (device globals; device-code access only) --------
__device__ float g_bias[NH*RELN];            // [h][rel + S-1]

__device__ uint32_t g_qhi_w[BSZ*NH*SEQ*(DK/2)];   // Q packed bf16 hi words
__device__ uint32_t g_qlo_w[BSZ*NH*SEQ*(DK/2)];
__device__ uint32_t g_khi_w[BSZ*NH*SEQ*(DK/2)];   // K packed bf16 words
__device__ uint32_t g_klo_w[BSZ*NH*SEQ*(DK/2)];
__device__ uint32_t g_vthi[BSZ*NH*DK*(SEQ/2)];    // V^T fp16 words [bh][d][u]

__device__ __nv_bfloat16 g_xhi[MROWS*DM];   // activations hi/lo (bf16)
__device__ __nv_bfloat16 g_xlo[MROWS*DM];
__device__ __nv_bfloat16 g_wth[4*DM*DM];    // W^T hi: [w][n][k]
__device__ __nv_bfloat16 g_wtl[4*DM*DM];    // W^T lo

// ======================= mma / ldmatrix / cp.async helpers ==================
__device__ __forceinline__ void mma_bf16(float acc[4], const uint32_t a[4],
                                         const uint32_t b[2]) {
    asm volatile(
        "mma.sync.aligned.m16n8k16.row.col.f32.bf16.bf16.f32 "
        "{%0,%1,%2,%3}, {%4,%5,%6,%7}, {%8,%9}, {%0,%1,%2,%3};"
        : "+f"(acc[0]), "+f"(acc[1]), "+f"(acc[2]), "+f"(acc[3])
        : "r"(a[0]), "r"(a[1]), "r"(a[2]), "r"(a[3]), "r"(b[0]), "r"(b[1]));
}
__device__ __forceinline__ void mma_f16f32(float acc[4], const uint32_t a[4],
                                           const uint32_t b[2]) {
    asm volatile(
        "mma.sync.aligned.m16n8k16.row.col.f32.f16.f16.f32 "
        "{%0,%1,%2,%3}, {%4,%5,%6,%7}, {%8,%9}, {%0,%1,%2,%3};"
        : "+f"(acc[0]), "+f"(acc[1]), "+f"(acc[2]), "+f"(acc[3])
        : "r"(a[0]), "r"(a[1]), "r"(a[2]), "r"(a[3]), "r"(b[0]), "r"(b[1]));
}
#define LDSM_X4(R0, R1, R2, R3, A) \
    asm volatile("ldmatrix.sync.aligned.m8n8.x4.shared.b16 {%0,%1,%2,%3}, [%4];" \
        : "=r"(R0), "=r"(R1), "=r"(R2), "=r"(R3) : "r"(A))
#define LDSM_X2(R0, R1, A) \
    asm volatile("ldmatrix.sync.aligned.m8n8.x2.shared.b16 {%0,%1}, [%2];" \
        : "=r"(R0), "=r"(R1) : "r"(A))
__device__ __forceinline__ uint32_t smem_u32(const void* p) {
    uint32_t a;
    asm("{ .reg .u64 t; cvta.to.shared.u64 t, %1; cvt.u32.u64 %0, t; }"
        : "=r"(a) : "l"(p));
    return a;
}
#define CP16(dst, src) \
    asm volatile("cp.async.cg.shared.global [%0], [%1], 16;" \
        :: "r"(dst), "l"(src))
#define CP_COMMIT() asm volatile("cp.async.commit_group;")
#define CP_WAIT(n)  asm volatile("cp.async.wait_group %0;" :: "n"(n))

__device__ __forceinline__ uint32_t packbf(float a, float b) {
    __nv_bfloat162 t;
    t.x = __float2bfloat16_rn(a);
    t.y = __float2bfloat16_rn(b);
    return *(uint32_t*)&t;
}
__device__ __forceinline__ void pack_hilo(float a, float b,
                                          uint32_t& hi, uint32_t& lo) {
    __nv_bfloat16 ha = __float2bfloat16_rn(a);
    __nv_bfloat16 hb = __float2bfloat16_rn(b);
    __nv_bfloat162 th; th.x = ha; th.y = hb;
    hi = *(uint32_t*)&th;
    lo = packbf(a - __bfloat162float(ha), b - __bfloat162float(hb));
}
__device__ __forceinline__ uint32_t packf16(float a, float b) {
    __half2 t = __floats2half2_rn(a, b);
    return *(uint32_t*)&t;
}

// ---------------- relative-position bias precompute -------------------------
__global__ void bias_kernel(const float* __restrict__ table) {
    int idx = blockIdx.x * blockDim.x + threadIdx.x;
    if (idx >= RELN) return;
    int rel = idx - (SEQ - 1);
    int bucket = (rel > 0) ? 16 : 0;
    int rabs = rel < 0 ? -rel : rel;
    int add;
    if (rabs < 8) {
        add = rabs;
    } else {
        double lf = log((double)rabs / 8.0) / log(16.0) * 8.0;
        add = 8 + (int)lf;
        if (add > 15) add = 15;
    }
    bucket += add;
#pragma unroll
    for (int h = 0; h < NH; h++)
        g_bias[h * RELN + idx] = table[bucket * NH + h];
}

// ---------------- fp32 X -> (hi,lo) bf16 split -------------------------------
__global__ __launch_bounds__(256) void xcvt(const float* __restrict__ in,
                                            int n4) {
    int i = blockIdx.x * blockDim.x + threadIdx.x;
    if (i >= n4) return;
    float4 x = ((const float4*)in)[i];
    float xs[4] = {x.x, x.y, x.z, x.w};
    __nv_bfloat16 hb[4], lb[4];
#pragma unroll
    for (int j = 0; j < 4; j++) {
        hb[j] = __float2bfloat16_rn(xs[j]);
        lb[j] = __float2bfloat16_rn(xs[j] - __bfloat162float(hb[j]));
    }
    *(uint2*)&g_xhi[i * 4] = *(uint2*)hb;
    *(uint2*)&g_xlo[i * 4] = *(uint2*)lb;
}

// ---------------- W [K][N] -> W^T (hi,lo) bf16 [N][K] -----------------------
__global__ __launch_bounds__(256) void wt_cvt(const float* __restrict__ Wq,
                                              const float* __restrict__ Wk,
                                              const float* __restrict__ Wv,
                                              const float* __restrict__ Wo) {
    __shared__ float tile[32][33];
    int w = blockIdx.z;
    const float* W = (w == 0) ? Wq : (w == 1) ? Wk : (w == 2) ? Wv : Wo;
    int kb = blockIdx.y * 32, nb = blockIdx.x * 32;
    int tx = threadIdx.x, ty = threadIdx.y;
    for (int r = ty; r < 32; r += 8)
        tile[r][tx] = W[(size_t)(kb + r) * DM + nb + tx];
    __syncthreads();
    __nv_bfloat16* oh = g_wth + (size_t)w * DM * DM;
    __nv_bfloat16* ol = g_wtl + (size_t)w * DM * DM;
    for (int r = ty; r < 32; r += 8) {
        float x = tile[tx][r];
        __nv_bfloat16 h = __float2bfloat16_rn(x);
        __nv_bfloat16 l = __float2bfloat16_rn(x - __bfloat162float(h));
        size_t o = (size_t)(nb + r) * DM + kb + tx;
        oh[o] = h;
        ol[o] = l;
    }
}

// ---------------- split-bf16 GEMM, one-barrier cp.async pipeline ------------
#define AW       2560
#define RSTRIDE  20
#define SLOT_W   (4*AW)
#define GEMM_SMEM_BYTES (2*SLOT_W*4)   // 81920
#define VPAD 133

__global__ __launch_bounds__(256, 2) void gemm_mma(
    int wbase, int mode, float* __restrict__ outp)
{
    extern __shared__ __align__(16) uint32_t gsm[];

    const int tid = threadIdx.x;
    const int wid = tid >> 5, lane = tid & 31;
    const int wm = wid & 1;
    const int wn = wid >> 1;
    const int fr = lane >> 2;
    const int fc = lane & 3;
    const int arow_l = (lane & 7) + ((lane >> 3) & 1) * 8;
    const int acol_l = (lane >> 4) * 4;
    const int brow_l = (lane & 7) + (lane >> 4) * 8;
    const int bcol_l = ((lane >> 3) & 1) * 4;

    const int w  = wbase + blockIdx.z;
    const int m0 = blockIdx.y * 128;
    const int n0 = blockIdx.x * 128;
    const __nv_bfloat16* __restrict__ ah = g_xhi;
    const __nv_bfloat16* __restrict__ al = g_xlo;
    const __nv_bfloat16* __restrict__ bh = g_wth + (size_t)w * DM * DM;
    const __nv_bfloat16* __restrict__ bl = g_wtl + (size_t)w * DM * DM;

    const __nv_bfloat16* asrc[4];
    const __nv_bfloat16* bsrc[4];
    uint32_t adst[4], bdst[4];
    const uint32_t sb0 = smem_u32(gsm);
#pragma unroll
    for (int i = 0; i < 4; i++) {
        int idx = tid + i * 256;
        int sel = idx >> 9, r = (idx >> 2) & 127, j = idx & 3;
        asrc[i] = (sel ? al : ah) + (size_t)(m0 + r) * DM + j * 8;
        adst[i] = sb0 + (uint32_t)(sel * AW + r * RSTRIDE + j * 4) * 4;
        bsrc[i] = (sel ? bl : bh) + (size_t)(n0 + r) * DM + j * 8;
        bdst[i] = sb0 + (uint32_t)(2 * AW + sel * AW + r * RSTRIDE + j * 4) * 4;
    }

    const int a_base_w = (wm * 64 + arow_l) * RSTRIDE + acol_l;
    const int b_base_w = (wn * 32 + brow_l) * RSTRIDE + bcol_l;

    float acc[4][4][4];
#pragma unroll
    for (int i = 0; i < 4; i++)
#pragma unroll
        for (int j = 0; j < 4; j++)
#pragma unroll
            for (int q = 0; q < 4; q++) acc[i][j][q] = 0.f;

    // prologue: prefetch chunk 0 into slot 0
#pragma unroll
    for (int i = 0; i < 4; i++) {
        CP16(adst[i], asrc[i]);
        CP16(bdst[i], bsrc[i]);
    }
    CP_COMMIT();

    for (int c = 0; c < 32; c++) {
        CP_WAIT(0);          // chunk c landed
        __syncthreads();     // visible to all; other slot fully consumed

        const uint32_t sws = sb0 + (c & 1) * (SLOT_W * 4);
#pragma unroll
        for (int ks = 0; ks < 2; ks++) {
            const int kw = ks * 8;
            uint32_t Af[4][4], Bhf[4][2], Blf[4][2];
#pragma unroll
            for (int mf = 0; mf < 4; mf++) {
                uint32_t ad = sws + (uint32_t)(a_base_w + mf * 16 * RSTRIDE + kw) * 4;
                LDSM_X4(Af[mf][0], Af[mf][1], Af[mf][2], Af[mf][3], ad);
            }
#pragma unroll
            for (int j = 0; j < 2; j++) {
                uint32_t bd = sws + (uint32_t)(2 * AW + b_base_w + j * 16 * RSTRIDE + kw) * 4;
                LDSM_X4(Bhf[2 * j][0], Bhf[2 * j][1],
                        Bhf[2 * j + 1][0], Bhf[2 * j + 1][1], bd);
                LDSM_X4(Blf[2 * j][0], Blf[2 * j][1],
                        Blf[2 * j + 1][0], Blf[2 * j + 1][1], bd + AW * 4);
            }
            if (ks == 0 && c < 31) {
                const int k1 = (c + 1) * 32;
                const uint32_t so = ((c + 1) & 1) * (SLOT_W * 4);
#pragma unroll
                for (int i = 0; i < 4; i++) {
                    CP16(adst[i] + so, asrc[i] + k1);
                    CP16(bdst[i] + so, bsrc[i] + k1);
                }
                CP_COMMIT();
            }
#pragma unroll
            for (int mf = 0; mf < 4; mf++)
#pragma unroll
                for (int nf = 0; nf < 4; nf++)
                    mma_bf16(acc[mf][nf], Af[mf], Bhf[nf]);   // hi*hi
#pragma unroll
            for (int mf = 0; mf < 4; mf++)
#pragma unroll
                for (int nf = 0; nf < 4; nf++)
                    mma_bf16(acc[mf][nf], Af[mf], Blf[nf]);   // hi*lo
#pragma unroll
            for (int mf = 0; mf < 4; mf++) {
                uint32_t ad = sws + (uint32_t)(AW + a_base_w + mf * 16 * RSTRIDE + kw) * 4;
                LDSM_X4(Af[mf][0], Af[mf][1], Af[mf][2], Af[mf][3], ad);
            }
#pragma unroll
            for (int mf = 0; mf < 4; mf++)
#pragma unroll
                for (int nf = 0; nf < 4; nf++)
                    mma_bf16(acc[mf][nf], Af[mf], Bhf[nf]);   // lo*hi
        }
    }

    // ---- epilogue ----
    if (mode == 0 && w == 2) {
        // V: transpose + pack single fp16 into g_vthi via smem staging
        __syncthreads();
        float* SMF = (float*)gsm;              // [128][VPAD]
#pragma unroll
        for (int mf = 0; mf < 4; mf++) {
            int rl = wm * 64 + mf * 16 + fr;
#pragma unroll
            for (int nf = 0; nf < 4; nf++) {
                int nl = wn * 32 + nf * 8 + fc * 2;
                SMF[rl * VPAD + nl]           = acc[mf][nf][0];
                SMF[rl * VPAD + nl + 1]       = acc[mf][nf][1];
                SMF[(rl + 8) * VPAD + nl]     = acc[mf][nf][2];
                SMF[(rl + 8) * VPAD + nl + 1] = acc[mf][nf][3];
            }
        }
        __syncthreads();
        const int b = m0 >> 11, s0 = m0 & (SEQ - 1);
#pragma unroll
        for (int i = 0; i < 32; i++) {
            int idx = tid + i * 256;
            int hh = idx >> 12, rem = idx & 4095;
            int d = rem >> 6, u = rem & 63;
            float v0 = SMF[(2 * u) * VPAD + hh * 64 + d];
            float v1 = SMF[(2 * u + 1) * VPAD + hh * 64 + d];
            int h = blockIdx.x * 2 + hh;
            size_t o = ((size_t)(b * NH + h) * DK + d) * (SEQ / 2) + (s0 >> 1) + u;
            g_vthi[o] = packf16(v0, v1);
        }
        return;
    }
#pragma unroll
    for (int mf = 0; mf < 4; mf++) {
        int row = m0 + wm * 64 + mf * 16 + fr;
#pragma unroll
        for (int nf = 0; nf < 4; nf++) {
            int n = n0 + wn * 32 + nf * 8 + fc * 2;
            if (mode == 0) {
                int h = n >> 6, d = n & 63;
                int b = row >> 11, s = row & (SEQ - 1);
                size_t wi = ((size_t)(b * NH + h) * SEQ + s) * (DK / 2) + (d >> 1);
                uint32_t* dsth = (w == 0) ? g_qhi_w : g_khi_w;
                uint32_t* dstl = (w == 0) ? g_qlo_w : g_klo_w;
                uint32_t hw, lw;
                pack_hilo(acc[mf][nf][0], acc[mf][nf][1], hw, lw);
                dsth[wi] = hw; dstl[wi] = lw;
                pack_hilo(acc[mf][nf][2], acc[mf][nf][3], hw, lw);
                dsth[wi + 8 * (DK / 2)] = hw;
                dstl[wi + 8 * (DK / 2)] = lw;
            } else {
                *(float2*)(outp + (size_t)row * DM + n) =
                    make_float2(acc[mf][nf][0], acc[mf][nf][1]);
                *(float2*)(outp + (size_t)(row + 8) * DM + n) =
                    make_float2(acc[mf][nf][2], acc[mf][nf][3]);
            }
        }
    }
}

// ---------------- flash attention, one-barrier cp.async pipeline ------------
#define KSTR 36
#define VSTR 68
#define S_KH 0
#define S_KL (128*KSTR)
#define S_VH (2*128*KSTR)
#define S_SB (S_VH + 64*VSTR)
#define SLOT3_W (S_SB + 256)
#define ATTN3_BYTES (2*SLOT3_W*4)   // 110720

__global__ __launch_bounds__(256, 1) void attn_mma() {
    extern __shared__ __align__(16) uint32_t SW3[];

    const int bh = blockIdx.y;
    const int h = bh & (NH - 1);
    const int b = bh >> 4;
    const int q0 = blockIdx.x * 128;
    const int tid = threadIdx.x;
    const int wid = tid >> 5, lane = tid & 31;
    const int fr = lane >> 2, fc = lane & 3;
    const int brow_l = (lane & 7) + (lane >> 4) * 8;
    const int bcol_l = ((lane >> 3) & 1) * 4;

    const size_t kwbase = (size_t)bh * SEQ * (DK / 2);
    const size_t vwbase = (size_t)bh * DK * (SEQ / 2);
    const uint32_t sb0 = smem_u32(SW3);

    uint32_t Qh[4][4], Ql[4][4];
    {
        const size_t qb = kwbase + (size_t)(q0 + 16 * wid + fr) * (DK / 2);
#pragma unroll
        for (int ks = 0; ks < 4; ks++) {
            size_t i0 = qb + ks * 8 + fc;
            Qh[ks][0] = g_qhi_w[i0];
            Qh[ks][1] = g_qhi_w[i0 + 8 * (DK / 2)];
            Qh[ks][2] = g_qhi_w[i0 + 4];
            Qh[ks][3] = g_qhi_w[i0 + 8 * (DK / 2) + 4];
            Ql[ks][0] = g_qlo_w[i0];
            Ql[ks][1] = g_qlo_w[i0 + 8 * (DK / 2)];
            Ql[ks][2] = g_qlo_w[i0 + 4];
            Ql[ks][3] = g_qlo_w[i0 + 8 * (DK / 2) + 4];
        }
    }

    float Oa[8][4];
#pragma unroll
    for (int i = 0; i < 8; i++)
#pragma unroll
        for (int q = 0; q < 4; q++) Oa[i][q] = 0.f;
    float m_a = -1e30f, m_b = -1e30f, l_a = 0.f, l_b = 0.f;

    const int sboff = 2 * fc - 16 * wid - fr + 128;

    auto prefetch = [&](int t) {
        const int slot = t & 1;
        const uint32_t sbase = sb0 + slot * SLOT3_W * 4;
        const int k0 = t * 128;
#pragma unroll
        for (int i = 0; i < 4; i++) {
            int idx = tid + i * 256;
            int r = idx >> 3, jc = idx & 7;
            size_t src = kwbase + (size_t)(k0 + r) * (DK / 2) + jc * 4;
            uint32_t doff = (uint32_t)(r * KSTR + jc * 4) * 4;
            CP16(sbase + S_KH * 4 + doff, g_khi_w + src);
            CP16(sbase + S_KL * 4 + doff, g_klo_w + src);
        }
#pragma unroll
        for (int i = 0; i < 4; i++) {
            int idx = tid + i * 256;
            int d = idx >> 4, jc = idx & 15;
            size_t src = vwbase + (size_t)d * (SEQ / 2) + (k0 >> 1) + jc * 4;
            uint32_t doff = (uint32_t)(d * VSTR + jc * 4) * 4;
            CP16(sbase + S_VH * 4 + doff, g_vthi + src);
        }
        {
            int gi = 2047 + k0 - q0 + tid - 128;
            gi = gi < 0 ? 0 : (gi > RELN - 1 ? RELN - 1 : gi);
            float bv = g_bias[h * RELN + gi];
            SW3[slot * SLOT3_W + S_SB + tid] = __float_as_uint(bv);
        }
    };

    prefetch(0);
    CP_COMMIT();

    for (int t = 0; t < SEQ / 128; t++) {
        CP_WAIT(0);
        __syncthreads();
        if (t < SEQ / 128 - 1) {
            prefetch(t + 1);
            CP_COMMIT();
        }

        const uint32_t sws = sb0 + (t & 1) * SLOT3_W * 4;
        const float* Sb = (const float*)(SW3 + (t & 1) * SLOT3_W + S_SB);

        // ---- phase 1: S = Q K^T (bf16 3-term split) ----
        float sc[16][4];
#pragma unroll
        for (int nf = 0; nf < 16; nf++)
#pragma unroll
            for (int q = 0; q < 4; q++) sc[nf][q] = 0.f;

#pragma unroll
        for (int ks = 0; ks < 4; ks++) {
            const int kw = ks * 8 + bcol_l;
#pragma unroll
            for (int j = 0; j < 8; j++) {
                uint32_t kd = sws + (uint32_t)(S_KH + (j * 16 + brow_l) * KSTR + kw) * 4;
                uint32_t bf0[2], bf1[2];
                LDSM_X4(bf0[0], bf0[1], bf1[0], bf1[1], kd);
                mma_bf16(sc[2 * j],     Qh[ks], bf0);
                mma_bf16(sc[2 * j + 1], Qh[ks], bf1);
                mma_bf16(sc[2 * j],     Ql[ks], bf0);
                mma_bf16(sc[2 * j + 1], Ql[ks], bf1);
                LDSM_X4(bf0[0], bf0[1], bf1[0], bf1[1],
                        kd + (S_KL - S_KH) * 4);
                mma_bf16(sc[2 * j],     Qh[ks], bf0);
                mma_bf16(sc[2 * j + 1], Qh[ks], bf1);
            }
        }

        // ---- bias add ----
        float pb0 = Sb[sboff - 8], pb1 = Sb[sboff - 7];
#pragma unroll
        for (int nf = 0; nf < 16; nf++) {
            float b0 = Sb[sboff + 8 * nf];
            float b1 = Sb[sboff + 8 * nf + 1];
            sc[nf][0] += b0;
            sc[nf][1] += b1;
            sc[nf][2] += pb0;
            sc[nf][3] += pb1;
            pb0 = b0; pb1 = b1;
        }

        // ---- online softmax ----
        float mxa = -1e30f, mxb = -1e30f;
#pragma unroll
        for (int nf = 0; nf < 16; nf++) {
            mxa = fmaxf(mxa, fmaxf(sc[nf][0], sc[nf][1]));
            mxb = fmaxf(mxb, fmaxf(sc[nf][2], sc[nf][3]));
        }
        mxa = fmaxf(mxa, __shfl_xor_sync(0xffffffffu, mxa, 1));
        mxa = fmaxf(mxa, __shfl_xor_sync(0xffffffffu, mxa, 2));
        mxb = fmaxf(mxb, __shfl_xor_sync(0xffffffffu, mxb, 1));
        mxb = fmaxf(mxb, __shfl_xor_sync(0xffffffffu, mxb, 2));
        float mna = fmaxf(m_a, mxa), mnb = fmaxf(m_b, mxb);
        float ca = __expf(m_a - mna), cb = __expf(m_b - mnb);
        float sa = 0.f, sb2 = 0.f;
#pragma unroll
        for (int nf = 0; nf < 16; nf++) {
            sc[nf][0] = __expf(sc[nf][0] - mna);
            sc[nf][1] = __expf(sc[nf][1] - mna);
            sc[nf][2] = __expf(sc[nf][2] - mnb);
            sc[nf][3] = __expf(sc[nf][3] - mnb);
            sa  += sc[nf][0] + sc[nf][1];
            sb2 += sc[nf][2] + sc[nf][3];
        }
        sa  += __shfl_xor_sync(0xffffffffu, sa, 1);
        sa  += __shfl_xor_sync(0xffffffffu, sa, 2);
        sb2 += __shfl_xor_sync(0xffffffffu, sb2, 1);
        sb2 += __shfl_xor_sync(0xffffffffu, sb2, 2);
        l_a = l_a * ca + sa;
        l_b = l_b * cb + sb2;
        m_a = mna; m_b = mnb;

#pragma unroll
        for (int i = 0; i < 8; i++) {
            Oa[i][0] *= ca; Oa[i][1] *= ca;
            Oa[i][2] *= cb; Oa[i][3] *= cb;
        }

        // ---- phase 2: O += P V (P fp16, V single fp16: 1 MMA per pair) ----
#pragma unroll
        for (int ks2 = 0; ks2 < 8; ks2++) {
            uint32_t Ph[4];
            Ph[0] = packf16(sc[2*ks2][0],   sc[2*ks2][1]);
            Ph[1] = packf16(sc[2*ks2][2],   sc[2*ks2][3]);
            Ph[2] = packf16(sc[2*ks2+1][0], sc[2*ks2+1][1]);
            Ph[3] = packf16(sc[2*ks2+1][2], sc[2*ks2+1][3]);
            const int kw2 = ks2 * 8 + bcol_l;
#pragma unroll
            for (int j = 0; j < 4; j++) {
                uint32_t vd = sws + (uint32_t)(S_VH + (j * 16 + brow_l) * VSTR + kw2) * 4;
                uint32_t bf0[2], bf1[2];
                LDSM_X4(bf0[0], bf0[1], bf1[0], bf1[1], vd);
                mma_f16f32(Oa[2 * j],     Ph, bf0);
                mma_f16f32(Oa[2 * j + 1], Ph, bf1);
            }
        }
    }

    // ---- epilogue: write hi/lo bf16 straight into g_xhi/g_xlo --------------
    float inva = 1.0f / l_a, invb = 1.0f / l_b;
    int ra = q0 + 16 * wid + fr;
#pragma unroll
    for (int nf2 = 0; nf2 < 8; nf2++) {
        int d = nf2 * 8 + 2 * fc;
        size_t ia = (size_t)(b * SEQ + ra) * DM + h * DK + d;
        size_t ib = ia + (size_t)8 * DM;
        uint32_t hw, lw;
        pack_hilo(Oa[nf2][0] * inva, Oa[nf2][1] * inva, hw, lw);
        *(uint32_t*)&g_xhi[ia] = hw;
        *(uint32_t*)&g_xlo[ia] = lw;
        pack_hilo(Oa[nf2][2] * invb, Oa[nf2][3] * invb, hw, lw);
        *(uint32_t*)&g_xhi[ib] = hw;
        *(uint32_t*)&g_xlo[ib] = lw;
    }
}

// ---------------- launch ----------------------------------------------------
extern "C" void kernel_launch(void* const* d_in, const int* in_sizes, int n_in,
                              void* d_out, int out_size) {
    const float* X   = (const float*)d_in[0];
    const float* Wq  = (const float*)d_in[1];
    const float* Wk  = (const float*)d_in[2];
    const float* Wv  = (const float*)d_in[3];
    const float* Wo  = (const float*)d_in[4];
    const float* tbl = (const float*)d_in[5];
    float* out = (float*)d_out;

    cudaFuncSetAttribute(attn_mma,
                         cudaFuncAttributeMaxDynamicSharedMemorySize,
                         ATTN3_BYTES);
    cudaFuncSetAttribute(gemm_mma,
                         cudaFuncAttributeMaxDynamicSharedMemorySize,
                         GEMM_SMEM_BYTES);

    bias_kernel<<<(RELN + 255) / 256, 256>>>(tbl);

    xcvt<<<(MROWS * DM / 4 + 255) / 256, 256>>>(X, MROWS * DM / 4);
    dim3 gw(DM / 32, DM / 32, 4);
    wt_cvt<<<gw, dim3(32, 8)>>>(Wq, Wk, Wv, Wo);

    dim3 g1(DM / 128, MROWS / 128, 3);
    gemm_mma<<<g1, 256, GEMM_SMEM_BYTES>>>(0, 0, nullptr);

    dim3 g2(SEQ / 128, BSZ * NH);
    attn_mma<<<g2, 256, ATTN3_BYTES>>>();

    dim3 g3(DM / 128, MROWS / 128, 1);
    gemm_mma<<<g3, 256, GEMM_SMEM_BYTES>>>(3, 1, out);
}

// round 16
// speedup vs baseline: 1.3934x; 1.0950x over previous
#include <cuda_runtime.h>
#include <cuda_bf16.h>
#include <cuda_fp16.h>
#include <math.h>
#include <stdint.h>

#define BSZ   2
#define SEQ   2048
#define DM    1024
#define NH    16
#define DK    64
#define RELN  (2*SEQ-1)   // 4095
#define MROWS (BSZ*SEQ)   // 4096

// ---------------- scratch (device globals; device-code access only) --------
__device__ float g_bias[NH*RELN];            // [h][rel + S-1]

__device__ uint32_t g_qhi_w[BSZ*NH*SEQ*(DK/2)];   // Q packed fp16 hi words
__device__ uint32_t g_qlo_w[BSZ*NH*SEQ*(DK/2)];   // Q packed fp16 lo words
__device__ uint32_t g_k16_w[BSZ*NH*SEQ*(DK/2)];   // K packed single fp16
__device__ uint32_t g_vthi[BSZ*NH*DK*(SEQ/2)];    // V^T fp16 words [bh][d][u]

__device__ __nv_bfloat16 g_xhi[MROWS*DM];   // activations hi/lo (bf16)
__device__ __nv_bfloat16 g_xlo[MROWS*DM];
__device__ __nv_bfloat16 g_wth[4*DM*DM];    // W^T hi: [w][n][k]
__device__ __nv_bfloat16 g_wtl[4*DM*DM];    // W^T lo

// ======================= mma / ldmatrix / cp.async helpers ==================
__device__ __forceinline__ void mma_bf16(float acc[4], const uint32_t a[4],
                                         const uint32_t b[2]) {
    asm volatile(
        "mma.sync.aligned.m16n8k16.row.col.f32.bf16.bf16.f32 "
        "{%0,%1,%2,%3}, {%4,%5,%6,%7}, {%8,%9}, {%0,%1,%2,%3};"
        : "+f"(acc[0]), "+f"(acc[1]), "+f"(acc[2]), "+f"(acc[3])
        : "r"(a[0]), "r"(a[1]), "r"(a[2]), "r"(a[3]), "r"(b[0]), "r"(b[1]));
}
__device__ __forceinline__ void mma_f16f32(float acc[4], const uint32_t a[4],
                                           const uint32_t b[2]) {
    asm volatile(
        "mma.sync.aligned.m16n8k16.row.col.f32.f16.f16.f32 "
        "{%0,%1,%2,%3}, {%4,%5,%6,%7}, {%8,%9}, {%0,%1,%2,%3};"
        : "+f"(acc[0]), "+f"(acc[1]), "+f"(acc[2]), "+f"(acc[3])
        : "r"(a[0]), "r"(a[1]), "r"(a[2]), "r"(a[3]), "r"(b[0]), "r"(b[1]));
}
#define LDSM_X4(R0, R1, R2, R3, A) \
    asm volatile("ldmatrix.sync.aligned.m8n8.x4.shared.b16 {%0,%1,%2,%3}, [%4];" \
        : "=r"(R0), "=r"(R1), "=r"(R2), "=r"(R3) : "r"(A))
__device__ __forceinline__ uint32_t smem_u32(const void* p) {
    uint32_t a;
    asm("{ .reg .u64 t; cvta.to.shared.u64 t, %1; cvt.u32.u64 %0, t; }"
        : "=r"(a) : "l"(p));
    return a;
}
#define CP16(dst, src) \
    asm volatile("cp.async.cg.shared.global [%0], [%1], 16;" \
        :: "r"(dst), "l"(src))
#define CP_COMMIT() asm volatile("cp.async.commit_group;")
#define CP_WAIT(n)  asm volatile("cp.async.wait_group %0;" :: "n"(n))

__device__ __forceinline__ uint32_t packbf(float a, float b) {
    __nv_bfloat162 t;
    t.x = __float2bfloat16_rn(a);
    t.y = __float2bfloat16_rn(b);
    return *(uint32_t*)&t;
}
__device__ __forceinline__ void pack_hilo(float a, float b,
                                          uint32_t& hi, uint32_t& lo) {
    __nv_bfloat16 ha = __float2bfloat16_rn(a);
    __nv_bfloat16 hb = __float2bfloat16_rn(b);
    __nv_bfloat162 th; th.x = ha; th.y = hb;
    hi = *(uint32_t*)&th;
    lo = packbf(a - __bfloat162float(ha), b - __bfloat162float(hb));
}
__device__ __forceinline__ uint32_t packf16(float a, float b) {
    __half2 t = __floats2half2_rn(a, b);
    return *(uint32_t*)&t;
}
__device__ __forceinline__ void pack_hilo_f16(float a, float b,
                                              uint32_t& hi, uint32_t& lo) {
    __half ha = __float2half_rn(a);
    __half hb = __float2half_rn(b);
    __half2 H = __halves2half2(ha, hb);
    hi = *(uint32_t*)&H;
    lo = packf16(a - __half2float(ha), b - __half2float(hb));
}

// ---------------- relative-position bias precompute -------------------------
__global__ void bias_kernel(const float* __restrict__ table) {
    int idx = blockIdx.x * blockDim.x + threadIdx.x;
    if (idx >= RELN) return;
    int rel = idx - (SEQ - 1);
    int bucket = (rel > 0) ? 16 : 0;
    int rabs = rel < 0 ? -rel : rel;
    int add;
    if (rabs < 8) {
        add = rabs;
    } else {
        double lf = log((double)rabs / 8.0) / log(16.0) * 8.0;
        add = 8 + (int)lf;
        if (add > 15) add = 15;
    }
    bucket += add;
#pragma unroll
    for (int h = 0; h < NH; h++)
        g_bias[h * RELN + idx] = table[bucket * NH + h];
}

// ---------------- fp32 X -> (hi,lo) bf16 split -------------------------------
__global__ __launch_bounds__(256) void xcvt(const float* __restrict__ in,
                                            int n4) {
    int i = blockIdx.x * blockDim.x + threadIdx.x;
    if (i >= n4) return;
    float4 x = ((const float4*)in)[i];
    float xs[4] = {x.x, x.y, x.z, x.w};
    __nv_bfloat16 hb[4], lb[4];
#pragma unroll
    for (int j = 0; j < 4; j++) {
        hb[j] = __float2bfloat16_rn(xs[j]);
        lb[j] = __float2bfloat16_rn(xs[j] - __bfloat162float(hb[j]));
    }
    *(uint2*)&g_xhi[i * 4] = *(uint2*)hb;
    *(uint2*)&g_xlo[i * 4] = *(uint2*)lb;
}

// ---------------- W [K][N] -> W^T (hi,lo) bf16 [N][K] -----------------------
__global__ __launch_bounds__(256) void wt_cvt(const float* __restrict__ Wq,
                                              const float* __restrict__ Wk,
                                              const float* __restrict__ Wv,
                                              const float* __restrict__ Wo) {
    __shared__ float tile[32][33];
    int w = blockIdx.z;
    const float* W = (w == 0) ? Wq : (w == 1) ? Wk : (w == 2) ? Wv : Wo;
    int kb = blockIdx.y * 32, nb = blockIdx.x * 32;
    int tx = threadIdx.x, ty = threadIdx.y;
    for (int r = ty; r < 32; r += 8)
        tile[r][tx] = W[(size_t)(kb + r) * DM + nb + tx];
    __syncthreads();
    __nv_bfloat16* oh = g_wth + (size_t)w * DM * DM;
    __nv_bfloat16* ol = g_wtl + (size_t)w * DM * DM;
    for (int r = ty; r < 32; r += 8) {
        float x = tile[tx][r];
        __nv_bfloat16 h = __float2bfloat16_rn(x);
        __nv_bfloat16 l = __float2bfloat16_rn(x - __bfloat162float(h));
        size_t o = (size_t)(nb + r) * DM + kb + tx;
        oh[o] = h;
        ol[o] = l;
    }
}

// ---------------- split-bf16 GEMM, one-barrier cp.async pipeline ------------
#define AW       2560
#define RSTRIDE  20
#define SLOT_W   (4*AW)
#define GEMM_SMEM_BYTES (2*SLOT_W*4)   // 81920
#define VPAD 133

__global__ __launch_bounds__(256, 2) void gemm_mma(
    int wbase, int mode, float* __restrict__ outp)
{
    extern __shared__ __align__(16) uint32_t gsm[];

    const int tid = threadIdx.x;
    const int wid = tid >> 5, lane = tid & 31;
    const int wm = wid & 1;
    const int wn = wid >> 1;
    const int fr = lane >> 2;
    const int fc = lane & 3;
    const int arow_l = (lane & 7) + ((lane >> 3) & 1) * 8;
    const int acol_l = (lane >> 4) * 4;
    const int brow_l = (lane & 7) + (lane >> 4) * 8;
    const int bcol_l = ((lane >> 3) & 1) * 4;

    const int w  = wbase + blockIdx.z;
    const int m0 = blockIdx.y * 128;
    const int n0 = blockIdx.x * 128;
    const __nv_bfloat16* __restrict__ ah = g_xhi;
    const __nv_bfloat16* __restrict__ al = g_xlo;
    const __nv_bfloat16* __restrict__ bh = g_wth + (size_t)w * DM * DM;
    const __nv_bfloat16* __restrict__ bl = g_wtl + (size_t)w * DM * DM;

    const __nv_bfloat16* asrc[4];
    const __nv_bfloat16* bsrc[4];
    uint32_t adst[4], bdst[4];
    const uint32_t sb0 = smem_u32(gsm);
#pragma unroll
    for (int i = 0; i < 4; i++) {
        int idx = tid + i * 256;
        int sel = idx >> 9, r = (idx >> 2) & 127, j = idx & 3;
        asrc[i] = (sel ? al : ah) + (size_t)(m0 + r) * DM + j * 8;
        adst[i] = sb0 + (uint32_t)(sel * AW + r * RSTRIDE + j * 4) * 4;
        bsrc[i] = (sel ? bl : bh) + (size_t)(n0 + r) * DM + j * 8;
        bdst[i] = sb0 + (uint32_t)(2 * AW + sel * AW + r * RSTRIDE + j * 4) * 4;
    }

    const int a_base_w = (wm * 64 + arow_l) * RSTRIDE + acol_l;
    const int b_base_w = (wn * 32 + brow_l) * RSTRIDE + bcol_l;

    float acc[4][4][4];
#pragma unroll
    for (int i = 0; i < 4; i++)
#pragma unroll
        for (int j = 0; j < 4; j++)
#pragma unroll
            for (int q = 0; q < 4; q++) acc[i][j][q] = 0.f;

    // prologue: prefetch chunk 0 into slot 0
#pragma unroll
    for (int i = 0; i < 4; i++) {
        CP16(adst[i], asrc[i]);
        CP16(bdst[i], bsrc[i]);
    }
    CP_COMMIT();

    for (int c = 0; c < 32; c++) {
        CP_WAIT(0);          // chunk c landed
        __syncthreads();     // visible to all; other slot fully consumed

        const uint32_t sws = sb0 + (c & 1) * (SLOT_W * 4);
#pragma unroll
        for (int ks = 0; ks < 2; ks++) {
            const int kw = ks * 8;
            uint32_t Af[4][4], Bhf[4][2], Blf[4][2];
#pragma unroll
            for (int mf = 0; mf < 4; mf++) {
                uint32_t ad = sws + (uint32_t)(a_base_w + mf * 16 * RSTRIDE + kw) * 4;
                LDSM_X4(Af[mf][0], Af[mf][1], Af[mf][2], Af[mf][3], ad);
            }
#pragma unroll
            for (int j = 0; j < 2; j++) {
                uint32_t bd = sws + (uint32_t)(2 * AW + b_base_w + j * 16 * RSTRIDE + kw) * 4;
                LDSM_X4(Bhf[2 * j][0], Bhf[2 * j][1],
                        Bhf[2 * j + 1][0], Bhf[2 * j + 1][1], bd);
                LDSM_X4(Blf[2 * j][0], Blf[2 * j][1],
                        Blf[2 * j + 1][0], Blf[2 * j + 1][1], bd + AW * 4);
            }
            if (ks == 0 && c < 31) {
                const int k1 = (c + 1) * 32;
                const uint32_t so = ((c + 1) & 1) * (SLOT_W * 4);
#pragma unroll
                for (int i = 0; i < 4; i++) {
                    CP16(adst[i] + so, asrc[i] + k1);
                    CP16(bdst[i] + so, bsrc[i] + k1);
                }
                CP_COMMIT();
            }
#pragma unroll
            for (int mf = 0; mf < 4; mf++)
#pragma unroll
                for (int nf = 0; nf < 4; nf++)
                    mma_bf16(acc[mf][nf], Af[mf], Bhf[nf]);   // hi*hi
#pragma unroll
            for (int mf = 0; mf < 4; mf++)
#pragma unroll
                for (int nf = 0; nf < 4; nf++)
                    mma_bf16(acc[mf][nf], Af[mf], Blf[nf]);   // hi*lo
#pragma unroll
            for (int mf = 0; mf < 4; mf++) {
                uint32_t ad = sws + (uint32_t)(AW + a_base_w + mf * 16 * RSTRIDE + kw) * 4;
                LDSM_X4(Af[mf][0], Af[mf][1], Af[mf][2], Af[mf][3], ad);
            }
#pragma unroll
            for (int mf = 0; mf < 4; mf++)
#pragma unroll
                for (int nf = 0; nf < 4; nf++)
                    mma_bf16(acc[mf][nf], Af[mf], Bhf[nf]);   // lo*hi
        }
    }

    // ---- epilogue ----
    if (mode == 0 && w == 2) {
        // V: transpose + pack single fp16 into g_vthi via smem staging
        __syncthreads();
        float* SMF = (float*)gsm;              // [128][VPAD]
#pragma unroll
        for (int mf = 0; mf < 4; mf++) {
            int rl = wm * 64 + mf * 16 + fr;
#pragma unroll
            for (int nf = 0; nf < 4; nf++) {
                int nl = wn * 32 + nf * 8 + fc * 2;
                SMF[rl * VPAD + nl]           = acc[mf][nf][0];
                SMF[rl * VPAD + nl + 1]       = acc[mf][nf][1];
                SMF[(rl + 8) * VPAD + nl]     = acc[mf][nf][2];
                SMF[(rl + 8) * VPAD + nl + 1] = acc[mf][nf][3];
            }
        }
        __syncthreads();
        const int b = m0 >> 11, s0 = m0 & (SEQ - 1);
#pragma unroll
        for (int i = 0; i < 32; i++) {
            int idx = tid + i * 256;
            int hh = idx >> 12, rem = idx & 4095;
            int d = rem >> 6, u = rem & 63;
            float v0 = SMF[(2 * u) * VPAD + hh * 64 + d];
            float v1 = SMF[(2 * u + 1) * VPAD + hh * 64 + d];
            int h = blockIdx.x * 2 + hh;
            size_t o = ((size_t)(b * NH + h) * DK + d) * (SEQ / 2) + (s0 >> 1) + u;
            g_vthi[o] = packf16(v0, v1);
        }
        return;
    }
#pragma unroll
    for (int mf = 0; mf < 4; mf++) {
        int row = m0 + wm * 64 + mf * 16 + fr;
#pragma unroll
        for (int nf = 0; nf < 4; nf++) {
            int n = n0 + wn * 32 + nf * 8 + fc * 2;
            if (mode == 0) {
                int h = n >> 6, d = n & 63;
                int b = row >> 11, s = row & (SEQ - 1);
                size_t wi = ((size_t)(b * NH + h) * SEQ + s) * (DK / 2) + (d >> 1);
                if (w == 0) {
                    uint32_t hw, lw;
                    pack_hilo_f16(acc[mf][nf][0], acc[mf][nf][1], hw, lw);
                    g_qhi_w[wi] = hw; g_qlo_w[wi] = lw;
                    pack_hilo_f16(acc[mf][nf][2], acc[mf][nf][3], hw, lw);
                    g_qhi_w[wi + 8 * (DK / 2)] = hw;
                    g_qlo_w[wi + 8 * (DK / 2)] = lw;
                } else {
                    g_k16_w[wi] = packf16(acc[mf][nf][0], acc[mf][nf][1]);
                    g_k16_w[wi + 8 * (DK / 2)] =
                        packf16(acc[mf][nf][2], acc[mf][nf][3]);
                }
            } else {
                *(float2*)(outp + (size_t)row * DM + n) =
                    make_float2(acc[mf][nf][0], acc[mf][nf][1]);
                *(float2*)(outp + (size_t)(row + 8) * DM + n) =
                    make_float2(acc[mf][nf][2], acc[mf][nf][3]);
            }
        }
    }
}

// ---------------- flash attention, one-barrier cp.async pipeline ------------
#define KSTR 36
#define VSTR 68
#define S_K  0
#define S_VH (128*KSTR)             // 4608
#define S_SB (S_VH + 64*VSTR)       // 8960
#define SLOT3_W (S_SB + 256)        // 9216
#define ATTN3_BYTES (2*SLOT3_W*4)   // 73728

__global__ __launch_bounds__(256, 1) void attn_mma() {
    extern __shared__ __align__(16) uint32_t SW3[];

    const int bh = blockIdx.y;
    const int h = bh & (NH - 1);
    const int b = bh >> 4;
    const int q0 = blockIdx.x * 128;
    const int tid = threadIdx.x;
    const int wid = tid >> 5, lane = tid & 31;
    const int fr = lane >> 2, fc = lane & 3;
    const int brow_l = (lane & 7) + (lane >> 4) * 8;
    const int bcol_l = ((lane >> 3) & 1) * 4;

    const size_t kwbase = (size_t)bh * SEQ * (DK / 2);
    const size_t vwbase = (size_t)bh * DK * (SEQ / 2);
    const uint32_t sb0 = smem_u32(SW3);

    uint32_t Qh[4][4], Ql[4][4];
    {
        const size_t qb = kwbase + (size_t)(q0 + 16 * wid + fr) * (DK / 2);
#pragma unroll
        for (int ks = 0; ks < 4; ks++) {
            size_t i0 = qb + ks * 8 + fc;
            Qh[ks][0] = g_qhi_w[i0];
            Qh[ks][1] = g_qhi_w[i0 + 8 * (DK / 2)];
            Qh[ks][2] = g_qhi_w[i0 + 4];
            Qh[ks][3] = g_qhi_w[i0 + 8 * (DK / 2) + 4];
            Ql[ks][0] = g_qlo_w[i0];
            Ql[ks][1] = g_qlo_w[i0 + 8 * (DK / 2)];
            Ql[ks][2] = g_qlo_w[i0 + 4];
            Ql[ks][3] = g_qlo_w[i0 + 8 * (DK / 2) + 4];
        }
    }

    float Oa[8][4];
#pragma unroll
    for (int i = 0; i < 8; i++)
#pragma unroll
        for (int q = 0; q < 4; q++) Oa[i][q] = 0.f;
    float m_a = -1e30f, m_b = -1e30f, l_a = 0.f, l_b = 0.f;

    const int sboff = 2 * fc - 16 * wid - fr + 128;

    auto prefetch = [&](int t) {
        const int slot = t & 1;
        const uint32_t sbase = sb0 + slot * SLOT3_W * 4;
        const int k0 = t * 128;
#pragma unroll
        for (int i = 0; i < 4; i++) {
            int idx = tid + i * 256;
            int r = idx >> 3, jc = idx & 7;
            size_t src = kwbase + (size_t)(k0 + r) * (DK / 2) + jc * 4;
            uint32_t doff = (uint32_t)(r * KSTR + jc * 4) * 4;
            CP16(sbase + S_K * 4 + doff, g_k16_w + src);
        }
#pragma unroll
        for (int i = 0; i < 4; i++) {
            int idx = tid + i * 256;
            int d = idx >> 4, jc = idx & 15;
            size_t src = vwbase + (size_t)d * (SEQ / 2) + (k0 >> 1) + jc * 4;
            uint32_t doff = (uint32_t)(d * VSTR + jc * 4) * 4;
            CP16(sbase + S_VH * 4 + doff, g_vthi + src);
        }
        {
            int gi = 2047 + k0 - q0 + tid - 128;
            gi = gi < 0 ? 0 : (gi > RELN - 1 ? RELN - 1 : gi);
            float bv = g_bias[h * RELN + gi];
            SW3[slot * SLOT3_W + S_SB + tid] = __float_as_uint(bv);
        }
    };

    prefetch(0);
    CP_COMMIT();

    for (int t = 0; t < SEQ / 128; t++) {
        CP_WAIT(0);
        __syncthreads();
        if (t < SEQ / 128 - 1) {
            prefetch(t + 1);
            CP_COMMIT();
        }

        const uint32_t sws = sb0 + (t & 1) * SLOT3_W * 4;
        const float* Sb = (const float*)(SW3 + (t & 1) * SLOT3_W + S_SB);

        // ---- phase 1: S = (Qh+Ql) * K16 (2 MMAs per subtile) ----
        float sc[16][4];
#pragma unroll
        for (int nf = 0; nf < 16; nf++)
#pragma unroll
            for (int q = 0; q < 4; q++) sc[nf][q] = 0.f;

#pragma unroll
        for (int ks = 0; ks < 4; ks++) {
            const int kw = ks * 8 + bcol_l;
#pragma unroll
            for (int j = 0; j < 8; j++) {
                uint32_t kd = sws + (uint32_t)(S_K + (j * 16 + brow_l) * KSTR + kw) * 4;
                uint32_t bf0[2], bf1[2];
                LDSM_X4(bf0[0], bf0[1], bf1[0], bf1[1], kd);
                mma_f16f32(sc[2 * j],     Qh[ks], bf0);
                mma_f16f32(sc[2 * j + 1], Qh[ks], bf1);
                mma_f16f32(sc[2 * j],     Ql[ks], bf0);
                mma_f16f32(sc[2 * j + 1], Ql[ks], bf1);
            }
        }

        // ---- bias add ----
        float pb0 = Sb[sboff - 8], pb1 = Sb[sboff - 7];
#pragma unroll
        for (int nf = 0; nf < 16; nf++) {
            float b0 = Sb[sboff + 8 * nf];
            float b1 = Sb[sboff + 8 * nf + 1];
            sc[nf][0] += b0;
            sc[nf][1] += b1;
            sc[nf][2] += pb0;
            sc[nf][3] += pb1;
            pb0 = b0; pb1 = b1;
        }

        // ---- online softmax ----
        float mxa = -1e30f, mxb = -1e30f;
#pragma unroll
        for (int nf = 0; nf < 16; nf++) {
            mxa = fmaxf(mxa, fmaxf(sc[nf][0], sc[nf][1]));
            mxb = fmaxf(mxb, fmaxf(sc[nf][2], sc[nf][3]));
        }
        mxa = fmaxf(mxa, __shfl_xor_sync(0xffffffffu, mxa, 1));
        mxa = fmaxf(mxa, __shfl_xor_sync(0xffffffffu, mxa, 2));
        mxb = fmaxf(mxb, __shfl_xor_sync(0xffffffffu, mxb, 1));
        mxb = fmaxf(mxb, __shfl_xor_sync(0xffffffffu, mxb, 2));
        float mna = fmaxf(m_a, mxa), mnb = fmaxf(m_b, mxb);
        float ca = __expf(m_a - mna), cb = __expf(m_b - mnb);
        float sa = 0.f, sb2 = 0.f;
#pragma unroll
        for (int nf = 0; nf < 16; nf++) {
            sc[nf][0] = __expf(sc[nf][0] - mna);
            sc[nf][1] = __expf(sc[nf][1] - mna);
            sc[nf][2] = __expf(sc[nf][2] - mnb);
            sc[nf][3] = __expf(sc[nf][3] - mnb);
            sa  += sc[nf][0] + sc[nf][1];
            sb2 += sc[nf][2] + sc[nf][3];
        }
        sa  += __shfl_xor_sync(0xffffffffu, sa, 1);
        sa  += __shfl_xor_sync(0xffffffffu, sa, 2);
        sb2 += __shfl_xor_sync(0xffffffffu, sb2, 1);
        sb2 += __shfl_xor_sync(0xffffffffu, sb2, 2);
        l_a = l_a * ca + sa;
        l_b = l_b * cb + sb2;
        m_a = mna; m_b = mnb;

#pragma unroll
        for (int i = 0; i < 8; i++) {
            Oa[i][0] *= ca; Oa[i][1] *= ca;
            Oa[i][2] *= cb; Oa[i][3] *= cb;
        }

        // ---- phase 2: O += P V (P fp16, V single fp16: 1 MMA per pair) ----
#pragma unroll
        for (int ks2 = 0; ks2 < 8; ks2++) {
            uint32_t Ph[4];
            Ph[0] = packf16(sc[2*ks2][0],   sc[2*ks2][1]);
            Ph[1] = packf16(sc[2*ks2][2],   sc[2*ks2][3]);
            Ph[2] = packf16(sc[2*ks2+1][0], sc[2*ks2+1][1]);
            Ph[3] = packf16(sc[2*ks2+1][2], sc[2*ks2+1][3]);
            const int kw2 = ks2 * 8 + bcol_l;
#pragma unroll
            for (int j = 0; j < 4; j++) {
                uint32_t vd = sws + (uint32_t)(S_VH + (j * 16 + brow_l) * VSTR + kw2) * 4;
                uint32_t bf0[2], bf1[2];
                LDSM_X4(bf0[0], bf0[1], bf1[0], bf1[1], vd);
                mma_f16f32(Oa[2 * j],     Ph, bf0);
                mma_f16f32(Oa[2 * j + 1], Ph, bf1);
            }
        }
    }

    // ---- epilogue: write hi/lo bf16 straight into g_xhi/g_xlo --------------
    float inva = 1.0f / l_a, invb = 1.0f / l_b;
    int ra = q0 + 16 * wid + fr;
#pragma unroll
    for (int nf2 = 0; nf2 < 8; nf2++) {
        int d = nf2 * 8 + 2 * fc;
        size_t ia = (size_t)(b * SEQ + ra) * DM + h * DK + d;
        size_t ib = ia + (size_t)8 * DM;
        uint32_t hw, lw;
        pack_hilo(Oa[nf2][0] * inva, Oa[nf2][1] * inva, hw, lw);
        *(uint32_t*)&g_xhi[ia] = hw;
        *(uint32_t*)&g_xlo[ia] = lw;
        pack_hilo(Oa[nf2][2] * invb, Oa[nf2][3] * invb, hw, lw);
        *(uint32_t*)&g_xhi[ib] = hw;
        *(uint32_t*)&g_xlo[ib] = lw;
    }
}

// ---------------- launch ----------------------------------------------------
extern "C" void kernel_launch(void* const* d_in, const int* in_sizes, int n_in,
                              void* d_out, int out_size) {
    const float* X   = (const float*)d_in[0];
    const float* Wq  = (const float*)d_in[1];
    const float* Wk  = (const float*)d_in[2];
    const float* Wv  = (const float*)d_in[3];
    const float* Wo  = (const float*)d_in[4];
    const float* tbl = (const float*)d_in[5];
    float* out = (float*)d_out;

    cudaFuncSetAttribute(attn_mma,
                         cudaFuncAttributeMaxDynamicSharedMemorySize,
                         ATTN3_BYTES);
    cudaFuncSetAttribute(gemm_mma,
                         cudaFuncAttributeMaxDynamicSharedMemorySize,
                         GEMM_SMEM_BYTES);

    bias_kernel<<<(RELN + 255) / 256, 256>>>(tbl);

    xcvt<<<(MROWS * DM / 4 + 255) / 256, 256>>>(X, MROWS * DM / 4);
    dim3 gw(DM / 32, DM / 32, 4);
    wt_cvt<<<gw, dim3(32, 8)>>>(Wq, Wk, Wv, Wo);

    dim3 g1(DM / 128, MROWS / 128, 3);
    gemm_mma<<<g1, 256, GEMM_SMEM_BYTES>>>(0, 0, nullptr);

    dim3 g2(SEQ / 128, BSZ * NH);
    attn_mma<<<g2, 256, ATTN3_BYTES>>>();

    dim3 g3(DM / 128, MROWS / 128, 1);
    gemm_mma<<<g3, 256, GEMM_SMEM_BYTES>>>(3, 1, out);
}